// round 6
// baseline (speedup 1.0000x reference)
#include <cuda_runtime.h>
#include <cuda_fp16.h>
#include <math.h>
#include <stdint.h>

// Problem dims (fixed by reference setup_inputs)
#define NB     16
#define SS     512
#define HH     1024
#define VV     8000
#define LLAY   8
#define NHEADS 4
#define DHEAD  256
#define NTOK   (NB*SS)          // 8192

// ---------------- scratch (__device__ globals: no allocation allowed) ---------
__device__ float g_z [NTOK*HH];
__device__ float g_z1[NTOK*HH];
__device__ float g_q [NTOK*HH];
__device__ float g_k [NTOK*HH];
__device__ float g_v [NTOK*HH];
__device__ float g_o [NTOK*HH];          // attention out, [B,H,S,dh] contiguous
__device__ float g_f [NTOK*HH];
__device__ float g_g [NTOK*HH];
__device__ float g_p [NB*NHEADS*SS*SS];  // attention probs, 64 MB

// ---------------- fp16 split helpers -----------------------------------------
// hi/lo split of (x,y), packed k-pair in one uint32 (low half = even k)
__device__ __forceinline__ void split2h(float x, float y, uint32_t& hi, uint32_t& lo){
    __half2 h = __floats2half2_rn(x, y);
    float rx = x - __half2float(__low2half(h));
    float ry = y - __half2float(__high2half(h));
    __half2 l = __floats2half2_rn(rx, ry);
    hi = *(uint32_t*)&h;
    lo = *(uint32_t*)&l;
}
__device__ __forceinline__ uint32_t pack2h(float x, float y){
    __half2 h = __floats2half2_rn(x, y);
    return *(uint32_t*)&h;
}

__device__ __forceinline__ void mma_f16(float* c, const uint32_t* a, const uint32_t* b){
    asm volatile("mma.sync.aligned.m16n8k16.row.col.f32.f16.f16.f32 "
        "{%0,%1,%2,%3}, {%4,%5,%6,%7}, {%8,%9}, {%0,%1,%2,%3};"
        : "+f"(c[0]),"+f"(c[1]),"+f"(c[2]),"+f"(c[3])
        : "r"(a[0]),"r"(a[1]),"r"(a[2]),"r"(a[3]), "r"(b[0]),"r"(b[1]));
}

// ================= fp16x2 tensor-core GEMM (double-buffered, 2 CTAs/SM) =======
// C = alpha*(A op(B)) + bias, optional exact GELU.
// A split hi+lo fp16; B rounded once to fp16 (dropped term ~2^-12 relative).
// BNT=true : NT, B row-major [N,K];  BNT=false: NN, B row-major [K,N].
// Tile 128x64x32, 256 threads, warps 2(m)x4(n), warp tile 64x16.
// Batched via blockIdx.z: off = (z/divz)*s1 + (z%divz)*s2.
// M,K multiples of 128/32; N multiple of 64 (all shapes here qualify).
template<bool BNT, int EPI>
__global__ void __launch_bounds__(256,2) tgemm(
    const float* __restrict__ A, const float* __restrict__ B,
    const float* __restrict__ bias, float* __restrict__ C,
    int M, int N, int K, int lda, int ldb, int ldc, float alpha,
    int divz, long long sA1, long long sA2, long long sB1, long long sB2,
    long long sC1, long long sC2)
{
    __shared__ uint32_t Ah[2][16][136], Al[2][16][136], Bh[2][16][72];

    const int z = blockIdx.z;
    A += (long long)(z/divz)*sA1 + (long long)(z%divz)*sA2;
    B += (long long)(z/divz)*sB1 + (long long)(z%divz)*sB2;
    C += (long long)(z/divz)*sC1 + (long long)(z%divz)*sC2;
    const int m0 = blockIdx.y*128, n0 = blockIdx.x*64;
    const int tid = threadIdx.x;
    const int wid = tid>>5, lane = tid&31;
    const int g = lane>>2, t = lane&3;
    const int m0w = (wid&1)*64, n0w = (wid>>1)*16;
    const int lrow = tid & 31;        // A LDG/STS mapping
    const int lc4  = tid >> 5;        // 0..7 (float4 slot within 32-k row)

    float acc[4][2][4];
#pragma unroll
    for (int i=0;i<4;i++)
#pragma unroll
        for (int j=0;j<2;j++)
#pragma unroll
            for (int r=0;r<4;r++) acc[i][j][r]=0.f;

    const int nch = K >> 5;
    float4 av[4], bv[2];

    // ---- LDG chunk c into regs ----
    auto ldg_chunk = [&](int c){
        const int kc = c*32;
#pragma unroll
        for (int i=0;i<4;i++)
            av[i] = *(const float4*)&A[(long long)(m0+lrow+32*i)*lda + kc + lc4*4];
        if (BNT){
            const int r = tid & 63, c8 = tid >> 6;   // rows 0..63, slots c8 & c8+4
            bv[0] = *(const float4*)&B[(long long)(n0+r)*ldb + kc + c8*4];
            bv[1] = *(const float4*)&B[(long long)(n0+r)*ldb + kc + (c8+4)*4];
        } else {
            const int p = tid >> 4, n4 = tid & 15;   // kpair p, 4 cols
            bv[0] = *(const float4*)&B[(long long)(kc+2*p  )*ldb + n0 + n4*4];
            bv[1] = *(const float4*)&B[(long long)(kc+2*p+1)*ldb + n0 + n4*4];
        }
    };
    // ---- split + STS into buffer bf ----
    auto sts_chunk = [&](int bf){
#pragma unroll
        for (int i=0;i<4;i++){
            int row = lrow + 32*i;
            uint32_t h0,l0,h1,l1;
            split2h(av[i].x, av[i].y, h0, l0);
            split2h(av[i].z, av[i].w, h1, l1);
            Ah[bf][2*lc4  ][row] = h0;  Al[bf][2*lc4  ][row] = l0;
            Ah[bf][2*lc4+1][row] = h1;  Al[bf][2*lc4+1][row] = l1;
        }
        if (BNT){
            const int r = tid & 63, c8 = tid >> 6;
            Bh[bf][2*c8  ][r] = pack2h(bv[0].x, bv[0].y);
            Bh[bf][2*c8+1][r] = pack2h(bv[0].z, bv[0].w);
            Bh[bf][2*(c8+4)  ][r] = pack2h(bv[1].x, bv[1].y);
            Bh[bf][2*(c8+4)+1][r] = pack2h(bv[1].z, bv[1].w);
        } else {
            const int p = tid >> 4, n4 = tid & 15;
            uint4 w;
            w.x = pack2h(bv[0].x, bv[1].x);
            w.y = pack2h(bv[0].y, bv[1].y);
            w.z = pack2h(bv[0].z, bv[1].z);
            w.w = pack2h(bv[0].w, bv[1].w);
            *(uint4*)&Bh[bf][p][n4*4] = w;
        }
    };

    // prologue: chunk 0 staged
    ldg_chunk(0);
    sts_chunk(0);
    __syncthreads();

    for (int c=0; c<nch; c++){
        const int bf = c & 1;
        if (c+1 < nch) ldg_chunk(c+1);   // LDG overlaps compute below

        // ---- compute: 2 k-steps of m16n8k16, 2 split terms (hi, lo) ----
#pragma unroll
        for (int ks=0; ks<2; ks++){
            const int pr = ks*8 + t;
            uint32_t ah[4][4], al[4][4], bh[2][2];
#pragma unroll
            for (int i=0;i<4;i++){
                int m = m0w + i*16 + g;
                ah[i][0] = Ah[bf][pr  ][m];   ah[i][1] = Ah[bf][pr  ][m+8];
                ah[i][2] = Ah[bf][pr+4][m];   ah[i][3] = Ah[bf][pr+4][m+8];
                al[i][0] = Al[bf][pr  ][m];   al[i][1] = Al[bf][pr  ][m+8];
                al[i][2] = Al[bf][pr+4][m];   al[i][3] = Al[bf][pr+4][m+8];
            }
#pragma unroll
            for (int j=0;j<2;j++){
                int n = n0w + j*8 + g;
                bh[j][0] = Bh[bf][pr][n];  bh[j][1] = Bh[bf][pr+4][n];
            }
#pragma unroll
            for (int j=0;j<2;j++)
#pragma unroll
                for (int i=0;i<4;i++) mma_f16(acc[i][j], ah[i], bh[j]);
#pragma unroll
            for (int j=0;j<2;j++)
#pragma unroll
                for (int i=0;i<4;i++) mma_f16(acc[i][j], al[i], bh[j]);
        }

        if (c+1 < nch){
            sts_chunk((c+1)&1);          // other buffer: no hazard
        }
        __syncthreads();                 // single barrier per chunk
    }

    // ---- epilogue (N multiple of 64: no guards) ----
#pragma unroll
    for (int i=0;i<4;i++){
        const int r0 = m0 + m0w + i*16 + g;
        const int r1 = r0 + 8;
#pragma unroll
        for (int j=0;j<2;j++){
            const int col = n0 + n0w + j*8 + 2*t;
            float b0=0.f, b1=0.f;
            if (bias){ b0 = bias[col]; b1 = bias[col+1]; }
            float c0 = acc[i][j][0]*alpha + b0;
            float c1 = acc[i][j][1]*alpha + b1;
            float c2 = acc[i][j][2]*alpha + b0;
            float c3 = acc[i][j][3]*alpha + b1;
            if (EPI==1){
                c0 = 0.5f*c0*(1.0f+erff(c0*0.70710678118654752440f));
                c1 = 0.5f*c1*(1.0f+erff(c1*0.70710678118654752440f));
                c2 = 0.5f*c2*(1.0f+erff(c2*0.70710678118654752440f));
                c3 = 0.5f*c3*(1.0f+erff(c3*0.70710678118654752440f));
            }
            *(float2*)&C[(long long)r0*ldc + col] = make_float2(c0,c1);
            *(float2*)&C[(long long)r1*ldc + col] = make_float2(c2,c3);
        }
    }
}

// ---------------- reductions -------------------------------------------------
__device__ __forceinline__ float warp_sum(float v){
#pragma unroll
    for(int o=16;o;o>>=1) v += __shfl_xor_sync(0xffffffffu,v,o);
    return v;
}
__device__ __forceinline__ float warp_max(float v){
#pragma unroll
    for(int o=16;o;o>>=1) v = fmaxf(v,__shfl_xor_sync(0xffffffffu,v,o));
    return v;
}
template<int NW>
__device__ __forceinline__ float block_sum(float v, float* sh){
    v = warp_sum(v);
    if((threadIdx.x&31)==0) sh[threadIdx.x>>5]=v;
    __syncthreads();
    float t=0.f;
#pragma unroll
    for(int i=0;i<NW;i++) t+=sh[i];
    __syncthreads();
    return t;
}
template<int NW>
__device__ __forceinline__ float block_max(float v, float* sh){
    v = warp_max(v);
    if((threadIdx.x&31)==0) sh[threadIdx.x>>5]=v;
    __syncthreads();
    float t=-1e30f;
#pragma unroll
    for(int i=0;i<NW;i++) t=fmaxf(t,sh[i]);
    __syncthreads();
    return t;
}

// ---------------- token embedding + sinusoidal PE ----------------------------
__global__ __launch_bounds__(256) void embed_kernel(
    const int* __restrict__ x, const float* __restrict__ emb, float* __restrict__ z)
{
    const int row = blockIdx.x;
    const int s = row & (SS-1);
    const int tok = x[row];
    const int t = threadIdx.x;
#pragma unroll
    for(int i=0;i<4;i++){
        int c = t + (i<<8);
        int half = c >> 1;
        float dv = expf(-(float)(2*half) * (9.210340371976184f/(float)HH));
        float ang = (float)s * dv;
        float pe = (c & 1) ? cosf(ang) : sinf(ang);
        z[(long long)row*HH + c] = emb[(long long)tok*HH + c] + pe;
    }
}

// ---------------- fused residual-add + LayerNorm -----------------------------
__global__ __launch_bounds__(256) void add_ln_kernel(
    const float* __restrict__ X, const float* __restrict__ R,
    const float* __restrict__ g, const float* __restrict__ b, float* __restrict__ out)
{
    __shared__ float sh[8];
    const long long row = blockIdx.x;
    const float* x = X + row*HH;
    const float* r = R + row*HH;
    const int t = threadIdx.x;
    float v[4]; float s=0.f;
#pragma unroll
    for(int i=0;i<4;i++){ int c=t+(i<<8); v[i]=x[c]+r[c]; s+=v[i]; }
    float mean = block_sum<8>(s, sh) * (1.0f/(float)HH);
    float sq=0.f;
#pragma unroll
    for(int i=0;i<4;i++){ float d=v[i]-mean; sq+=d*d; }
    float var = block_sum<8>(sq, sh) * (1.0f/(float)HH);
    float rstd = rsqrtf(var + 1e-5f);
    float* o = out + row*HH;
#pragma unroll
    for(int i=0;i<4;i++){ int c=t+(i<<8); o[c]=(v[i]-mean)*rstd*g[c]+b[c]; }
}

// ---------------- causal masked softmax over S, + atten_last=1/denominator ---
__global__ __launch_bounds__(128) void attn_softmax_kernel(
    float* __restrict__ P, const int* __restrict__ lengths, float* __restrict__ attn_out)
{
    __shared__ float sh[4];
    const int idx = blockIdx.x;
    const int q = idx & (SS-1);
    const int b = idx >> 11;
    float* p = P + (long long)idx*SS;
    const int t = threadIdx.x;
    if (q >= lengths[b]) {
#pragma unroll
        for(int i=0;i<4;i++) p[t+(i<<7)] = 0.f;
        if (attn_out && t==0) attn_out[idx] = 0.f;
        return;
    }
    float v[4]; float m=-1e30f;
#pragma unroll
    for(int i=0;i<4;i++){ int k=t+(i<<7); v[i]=(k<=q)?p[k]:-1e30f; m=fmaxf(m,v[i]); }
    m = block_max<4>(m, sh);
    float s=0.f;
#pragma unroll
    for(int i=0;i<4;i++){ v[i]=expf(v[i]-m); s+=v[i]; }
    s = block_sum<4>(s, sh);
    float r = 1.0f/s;
#pragma unroll
    for(int i=0;i<4;i++) p[t+(i<<7)] = v[i]*r;
    if (attn_out && t==0) attn_out[idx] = r;
}

// ---------------- in-place softmax over vocab (8000) -------------------------
__global__ __launch_bounds__(256) void vocab_softmax_kernel(float* __restrict__ logits)
{
    __shared__ float sh[8];
    const long long row = blockIdx.x;
    float* p = logits + row*VV;
    const int t = threadIdx.x;
    float v[32]; float m=-1e30f;
#pragma unroll
    for(int i=0;i<32;i++){ int k=t+(i<<8); v[i]=(k<VV)?p[k]:-1e30f; m=fmaxf(m,v[i]); }
    m = block_max<8>(m, sh);
    float s=0.f;
#pragma unroll
    for(int i=0;i<32;i++){ v[i]=expf(v[i]-m); s+=v[i]; }
    s = block_sum<8>(s, sh);
    float r = 1.0f/s;
#pragma unroll
    for(int i=0;i<32;i++){ int k=t+(i<<8); if(k<VV) p[k]=v[i]*r; }
}

// ---------------- host-side launch helper ------------------------------------
static void launch_tgemm(const float*A,const float*B,const float*bias,float*C,
    int M,int N,int K,int lda,int ldb,int ldc,float alpha,bool bnt,bool gelu_ep,
    int batch,int divz,long long sA1,long long sA2,long long sB1,long long sB2,
    long long sC1,long long sC2)
{
    dim3 grid(N/64, M/128, batch);
    if (bnt){
        if (gelu_ep)
            tgemm<true,1><<<grid,256>>>(A,B,bias,C,M,N,K,lda,ldb,ldc,alpha,divz,sA1,sA2,sB1,sB2,sC1,sC2);
        else
            tgemm<true,0><<<grid,256>>>(A,B,bias,C,M,N,K,lda,ldb,ldc,alpha,divz,sA1,sA2,sB1,sB2,sC1,sC2);
    } else {
        tgemm<false,0><<<grid,256>>>(A,B,bias,C,M,N,K,lda,ldb,ldc,alpha,divz,sA1,sA2,sB1,sB2,sC1,sC2);
    }
}

extern "C" void kernel_launch(void* const* d_in, const int* in_sizes, int n_in,
                              void* d_out, int out_size)
{
    const int*   x       = (const int*)  d_in[0];
    const int*   lengths = (const int*)  d_in[1];
    const float* emb     = (const float*)d_in[2];
    const float* Wq = (const float*)d_in[3];
    const float* bq = (const float*)d_in[4];
    const float* Wk = (const float*)d_in[5];
    const float* bk = (const float*)d_in[6];
    const float* Wv = (const float*)d_in[7];
    const float* bv = (const float*)d_in[8];
    const float* W1 = (const float*)d_in[9];
    const float* b1 = (const float*)d_in[10];
    const float* W2 = (const float*)d_in[11];
    const float* b2 = (const float*)d_in[12];
    const float* g1 = (const float*)d_in[13];
    const float* be1= (const float*)d_in[14];
    const float* g2 = (const float*)d_in[15];
    const float* be2= (const float*)d_in[16];
    const float* Wfc= (const float*)d_in[17];
    const float* bfc= (const float*)d_in[18];
    float* out      = (float*)d_out;
    float* attn_out = out + (long long)NB*SS*VV;

    float *z,*z1,*q,*k,*v,*o,*f,*gg,*p;
    cudaGetSymbolAddress((void**)&z,  g_z);
    cudaGetSymbolAddress((void**)&z1, g_z1);
    cudaGetSymbolAddress((void**)&q,  g_q);
    cudaGetSymbolAddress((void**)&k,  g_k);
    cudaGetSymbolAddress((void**)&v,  g_v);
    cudaGetSymbolAddress((void**)&o,  g_o);
    cudaGetSymbolAddress((void**)&f,  g_f);
    cudaGetSymbolAddress((void**)&gg, g_g);
    cudaGetSymbolAddress((void**)&p,  g_p);

    const long long SH  = (long long)SS*HH;
    const long long SS2 = (long long)SS*SS;
    const long long SD  = (long long)SS*DHEAD;

    embed_kernel<<<NTOK,256>>>(x, emb, z);

    for (int l=0;l<LLAY;l++){
        const float* Wq_l = Wq + (long long)l*HH*HH;
        const float* Wk_l = Wk + (long long)l*HH*HH;
        const float* Wv_l = Wv + (long long)l*HH*HH;
        const float* W1_l = W1 + (long long)l*HH*HH;
        const float* W2_l = W2 + (long long)l*HH*HH;

        // Q,K,V projections: [8192,1024] = z @ W^T + b   (NT)
        launch_tgemm(z, Wq_l, bq+l*HH, q, NTOK,HH,HH, HH,HH,HH, 1.f,true,false, 1,1,0,0,0,0,0,0);
        launch_tgemm(z, Wk_l, bk+l*HH, k, NTOK,HH,HH, HH,HH,HH, 1.f,true,false, 1,1,0,0,0,0,0,0);
        launch_tgemm(z, Wv_l, bv+l*HH, v, NTOK,HH,HH, HH,HH,HH, 1.f,true,false, 1,1,0,0,0,0,0,0);

        // scores: P[b,h] = Q_bh @ K_bh^T / 32   (NT, batch=64, z=b*4+h)
        launch_tgemm(q, k, nullptr, p, SS,SS,DHEAD, HH,HH,SS, 1.0f/32.0f, true,false,
                     NB*NHEADS, NHEADS,
                     SH, DHEAD, SH, DHEAD,
                     (long long)NHEADS*SS2, SS2);

        attn_softmax_kernel<<<NB*NHEADS*SS,128>>>(p, lengths, (l==LLAY-1)?attn_out:nullptr);

        // O[b,h] = P_bh @ V_bh   (NN), stored [B,H,S,dh] contiguous
        launch_tgemm(p, v, nullptr, o, SS,DHEAD,SS, SS,HH,DHEAD, 1.f,false,false,
                     NB*NHEADS, NHEADS,
                     (long long)NHEADS*SS2, SS2,
                     SH, DHEAD,
                     (long long)NHEADS*SD, SD);

        // faithful reshape bug == identity on flat memory: read g_o linearly
        add_ln_kernel<<<NTOK,256>>>(z, o, g1+l*HH, be1+l*HH, z1);

        // FFN: gelu(z1 @ W1^T + b1) @ W2^T + b2   (NT)
        launch_tgemm(z1, W1_l, b1+l*HH, f,  NTOK,HH,HH, HH,HH,HH, 1.f,true,true,  1,1,0,0,0,0,0,0);
        launch_tgemm(f,  W2_l, b2+l*HH, gg, NTOK,HH,HH, HH,HH,HH, 1.f,true,false, 1,1,0,0,0,0,0,0);

        add_ln_kernel<<<NTOK,256>>>(z1, gg, g2+l*HH, be2+l*HH, z);
    }

    // out_fc = z @ Wfc^T + bfc (reuse g_q)
    launch_tgemm(z, Wfc, bfc, q, NTOK,HH,HH, HH,HH,HH, 1.f,true,false, 1,1,0,0,0,0,0,0);
    // logits = out_fc @ emb^T, straight into d_out (8000 = 125*64 exact)
    launch_tgemm(q, emb, nullptr, out, NTOK,VV,HH, HH,HH,VV, 1.f,true,false, 1,1,0,0,0,0,0,0);
    vocab_softmax_kernel<<<NTOK,256>>>(out);
}

// round 7
// speedup vs baseline: 2.0555x; 2.0555x over previous
#include <cuda_runtime.h>
#include <cuda_bf16.h>
#include <math.h>
#include <stdint.h>

// Problem dims (fixed by reference setup_inputs)
#define NB     16
#define SS     512
#define HH     1024
#define VV     8000
#define VPAD   8064            // pad vocab to multiple of 128
#define LLAY   8
#define NHEADS 4
#define DHEAD  256
#define NTOK   (NB*SS)          // 8192

typedef __nv_bfloat16 bf16;
typedef __nv_bfloat162 bf162;

// ---------------- scratch (__device__ globals: no allocation allowed) ---------
__device__ float g_z  [NTOK*HH];
__device__ float g_z1 [NTOK*HH];
__device__ float g_v  [NTOK*HH];
__device__ float g_o  [NTOK*HH];
__device__ float g_gg [NTOK*HH];
__device__ float g_s  [NB*NHEADS*SS*SS];       // attention scores fp32

__device__ bf16 g_zh [NTOK*HH],  g_zl [NTOK*HH];
__device__ bf16 g_z1h[NTOK*HH],  g_z1l[NTOK*HH];
__device__ bf16 g_qh [NTOK*HH],  g_ql [NTOK*HH];
__device__ bf16 g_kh [NTOK*HH],  g_kl [NTOK*HH];
__device__ bf16 g_fh [NTOK*HH],  g_fl [NTOK*HH];
__device__ bf16 g_och[NTOK*HH],  g_ocl[NTOK*HH];   // out_fc split
__device__ bf16 g_vth[NTOK*HH],  g_vtl[NTOK*HH];   // V^T split [bh][dh][S]
__device__ bf16 g_ph [NB*NHEADS*SS*SS], g_pl [NB*NHEADS*SS*SS];

__device__ bf16 g_Wqh[LLAY*HH*HH], g_Wql[LLAY*HH*HH];
__device__ bf16 g_Wkh[LLAY*HH*HH], g_Wkl[LLAY*HH*HH];
__device__ bf16 g_Wvh[LLAY*HH*HH], g_Wvl[LLAY*HH*HH];
__device__ bf16 g_W1h[LLAY*HH*HH], g_W1l[LLAY*HH*HH];
__device__ bf16 g_W2h[LLAY*HH*HH], g_W2l[LLAY*HH*HH];
__device__ bf16 g_Wfh[HH*HH],      g_Wfl[HH*HH];
__device__ bf16 g_emh[VPAD*HH],    g_eml[VPAD*HH];

// ---------------- helpers -----------------------------------------------------
__device__ __forceinline__ void bsplit(float x, bf16& h, bf16& l){
    h = __float2bfloat16(x);
    l = __float2bfloat16(x - __bfloat162float(h));
}
__device__ __forceinline__ void mma_bf16(float* c, const uint32_t* a, const uint32_t* b){
    asm volatile("mma.sync.aligned.m16n8k16.row.col.f32.bf16.bf16.f32 "
        "{%0,%1,%2,%3}, {%4,%5,%6,%7}, {%8,%9}, {%0,%1,%2,%3};"
        : "+f"(c[0]),"+f"(c[1]),"+f"(c[2]),"+f"(c[3])
        : "r"(a[0]),"r"(a[1]),"r"(a[2]),"r"(a[3]), "r"(b[0]),"r"(b[1]));
}
__device__ __forceinline__ uint32_t s2u(const void* p){
    uint32_t a;
    asm("{ .reg .u64 t; cvta.to.shared.u64 t, %1; cvt.u32.u64 %0, t; }" : "=r"(a) : "l"(p));
    return a;
}
__device__ __forceinline__ void cp16(uint32_t dst, const void* src){
    asm volatile("cp.async.cg.shared.global [%0], [%1], 16;" :: "r"(dst), "l"(src));
}

// ================= bf16x3 NT GEMM: pre-split inputs, cp.async pipeline ========
// C = alpha*(A @ B^T) + bias; optional exact GELU; optional split output.
// A: (Ah,Al) bf16 [M][K] row-major, lda elems; B: (Bh,Bl) [N][K], ldb.
// Tile 128x128x32, 256 thr, warps 2(m)x4(n) = 64x32 each.
// SMEM layout per array: row-major 64B rows, 16B chunk swizzle: ch ^= (row>>1)&3.
// Batched via blockIdx.z: off = (z/divz)*s1 + (z%divz)*s2 (elements).
// M,K multiples of 128/32; N multiple of 128 (pad); store guard col<Nst.
#define STG_BYTES 32768     // 4 arrays x 8KB per stage

template<int EPI>
__global__ void __launch_bounds__(256,2) tgemm(
    const bf16* __restrict__ Ah, const bf16* __restrict__ Al,
    const bf16* __restrict__ Bh, const bf16* __restrict__ Bl,
    const float* __restrict__ bias,
    float* __restrict__ C, bf16* __restrict__ Ch, bf16* __restrict__ Cl,
    int M, int N, int K, int lda, int ldb, int ldc, float alpha, int Nst,
    int divz, long long sA1, long long sA2, long long sB1, long long sB2,
    long long sC1, long long sC2)
{
    extern __shared__ char smem[];
    const int z = blockIdx.z;
    const long long offA = (long long)(z/divz)*sA1 + (long long)(z%divz)*sA2;
    const long long offB = (long long)(z/divz)*sB1 + (long long)(z%divz)*sB2;
    const long long offC = (long long)(z/divz)*sC1 + (long long)(z%divz)*sC2;
    Ah += offA; Al += offA; Bh += offB; Bl += offB;

    const int m0 = blockIdx.y*128, n0 = blockIdx.x*128;
    const int tid = threadIdx.x;
    const int wid = tid>>5, lane = tid&31;
    const int g = lane>>2, t = lane&3;
    const int m0w = (wid&1)*64, n0w = (wid>>1)*32;
    const int swz = g>>1;

    const uint32_t sb = s2u(smem);
    // staging map: op idx = tid + 256*r -> row = idx>>2 (0..127), ch = idx&3
    const int srow = tid>>2;
    const int sch  = tid&3;
    const uint32_t soff0 = (uint32_t)(srow*64 + ((sch          ^ ((srow>>1)&3))<<4));
    const int srow1 = (tid+256)>>2;
    const int sch1  = tid&3;
    const uint32_t soff1 = (uint32_t)(srow1*64 + ((sch1 ^ ((srow1>>1)&3))<<4));

    float acc[4][4][4];
#pragma unroll
    for (int i=0;i<4;i++)
#pragma unroll
        for (int j=0;j<4;j++)
#pragma unroll
            for (int r=0;r<4;r++) acc[i][j][r]=0.f;

    const int nch = K >> 5;

    auto stage_chunk = [&](int c, int st){
        const uint32_t base = sb + (uint32_t)st*STG_BYTES;
        const int kc = c*32;
        // r = 0
        {
            const long long ga = (long long)(m0+srow)*lda + kc + sch*8;
            const long long gb = (long long)(n0+srow)*ldb + kc + sch*8;
            cp16(base +         soff0, Ah + ga);
            cp16(base +  8192 + soff0, Al + ga);
            cp16(base + 16384 + soff0, Bh + gb);
            cp16(base + 24576 + soff0, Bl + gb);
        }
        // r = 1
        {
            const long long ga = (long long)(m0+srow1)*lda + kc + sch1*8;
            const long long gb = (long long)(n0+srow1)*ldb + kc + sch1*8;
            cp16(base +         soff1, Ah + ga);
            cp16(base +  8192 + soff1, Al + ga);
            cp16(base + 16384 + soff1, Bh + gb);
            cp16(base + 24576 + soff1, Bl + gb);
        }
        asm volatile("cp.async.commit_group;");
    };

    stage_chunk(0,0);
    stage_chunk(1,1);

    for (int c=0; c<nch; c++){
        const int st = c & 1;
        if (c+1 < nch) asm volatile("cp.async.wait_group 1;");
        else           asm volatile("cp.async.wait_group 0;");
        __syncthreads();

        const char* base = smem + st*STG_BYTES;
#pragma unroll
        for (int ks=0; ks<2; ks++){
            const int cs0 = ((ks*2  ) ^ swz)*16 + 4*t;
            const int cs1 = ((ks*2+1) ^ swz)*16 + 4*t;
            uint32_t bh[4][2], bl[4][2];
#pragma unroll
            for (int j=0;j<4;j++){
                const int n = n0w + j*8 + g;
                const int o0 = n*64 + cs0, o1 = n*64 + cs1;
                bh[j][0] = *(const uint32_t*)(base + 16384 + o0);
                bh[j][1] = *(const uint32_t*)(base + 16384 + o1);
                bl[j][0] = *(const uint32_t*)(base + 24576 + o0);
                bl[j][1] = *(const uint32_t*)(base + 24576 + o1);
            }
#pragma unroll
            for (int i=0;i<4;i++){
                const int m = m0w + i*16 + g;
                const int p0 = m*64 + cs0, p1 = (m+8)*64 + cs0;
                const int p2 = m*64 + cs1, p3 = (m+8)*64 + cs1;
                uint32_t ah[4] = {
                    *(const uint32_t*)(base + p0), *(const uint32_t*)(base + p1),
                    *(const uint32_t*)(base + p2), *(const uint32_t*)(base + p3) };
                uint32_t al[4] = {
                    *(const uint32_t*)(base + 8192 + p0), *(const uint32_t*)(base + 8192 + p1),
                    *(const uint32_t*)(base + 8192 + p2), *(const uint32_t*)(base + 8192 + p3) };
#pragma unroll
                for (int j=0;j<4;j++){
                    mma_bf16(acc[i][j], ah, bh[j]);
                    mma_bf16(acc[i][j], al, bh[j]);
                    mma_bf16(acc[i][j], ah, bl[j]);
                }
            }
        }
        __syncthreads();
        if (c+2 < nch) stage_chunk(c+2, st);
    }

    // ---- epilogue ----
#pragma unroll
    for (int i=0;i<4;i++){
        const long long r0 = m0 + m0w + i*16 + g;
        const long long r1 = r0 + 8;
#pragma unroll
        for (int j=0;j<4;j++){
            const int col = n0 + n0w + j*8 + 2*t;
            if (col < Nst){
                float b0=0.f, b1=0.f;
                if (bias){ b0 = bias[col]; b1 = bias[col+1]; }
                float c0 = acc[i][j][0]*alpha + b0;
                float c1 = acc[i][j][1]*alpha + b1;
                float c2 = acc[i][j][2]*alpha + b0;
                float c3 = acc[i][j][3]*alpha + b1;
                if (EPI==1){
                    c0 = 0.5f*c0*(1.0f+erff(c0*0.70710678118654752440f));
                    c1 = 0.5f*c1*(1.0f+erff(c1*0.70710678118654752440f));
                    c2 = 0.5f*c2*(1.0f+erff(c2*0.70710678118654752440f));
                    c3 = 0.5f*c3*(1.0f+erff(c3*0.70710678118654752440f));
                }
                if (C){
                    *(float2*)&C[(offC + r0*ldc) + col] = make_float2(c0,c1);
                    *(float2*)&C[(offC + r1*ldc) + col] = make_float2(c2,c3);
                }
                if (Ch){
                    bf162 h0, l0, h1, l1;
                    bsplit(c0, h0.x, l0.x); bsplit(c1, h0.y, l0.y);
                    bsplit(c2, h1.x, l1.x); bsplit(c3, h1.y, l1.y);
                    *(bf162*)&Ch[(offC + r0*ldc) + col] = h0;
                    *(bf162*)&Cl[(offC + r0*ldc) + col] = l0;
                    *(bf162*)&Ch[(offC + r1*ldc) + col] = h1;
                    *(bf162*)&Cl[(offC + r1*ldc) + col] = l1;
                }
            }
        }
    }
}

// ---------------- elementwise split kernels -----------------------------------
__global__ __launch_bounds__(256) void split_kernel(
    const float* __restrict__ in, bf16* __restrict__ h, bf16* __restrict__ l, int n)
{
    int i = (blockIdx.x*256 + threadIdx.x)*4;
    if (i < n){
        float4 v = *(const float4*)&in[i];
        bf162 hh0, ll0, hh1, ll1;
        bsplit(v.x, hh0.x, ll0.x); bsplit(v.y, hh0.y, ll0.y);
        bsplit(v.z, hh1.x, ll1.x); bsplit(v.w, hh1.y, ll1.y);
        *(bf162*)&h[i]   = hh0;  *(bf162*)&l[i]   = ll0;
        *(bf162*)&h[i+2] = hh1;  *(bf162*)&l[i+2] = ll1;
    }
}
__global__ __launch_bounds__(256) void emb_split_pad_kernel(
    const float* __restrict__ emb, bf16* __restrict__ h, bf16* __restrict__ l)
{
    int i = (blockIdx.x*256 + threadIdx.x)*4;         // over VPAD*HH
    int row = i >> 10;
    float4 v = make_float4(0.f,0.f,0.f,0.f);
    if (row < VV) v = *(const float4*)&emb[(long long)row*HH + (i & 1023)];
    bf162 hh0, ll0, hh1, ll1;
    bsplit(v.x, hh0.x, ll0.x); bsplit(v.y, hh0.y, ll0.y);
    bsplit(v.z, hh1.x, ll1.x); bsplit(v.w, hh1.y, ll1.y);
    *(bf162*)&h[i]   = hh0;  *(bf162*)&l[i]   = ll0;
    *(bf162*)&h[i+2] = hh1;  *(bf162*)&l[i+2] = ll1;
}

// ---------------- V transpose + split: vt[(b,h)][d][s] ------------------------
__global__ __launch_bounds__(256) void transpose_split_v(
    const float* __restrict__ V, bf16* __restrict__ Vth, bf16* __restrict__ Vtl)
{
    __shared__ float tbuf[32][33];
    const int bh = blockIdx.z, b = bh >> 2, h = bh & 3;
    const int s0 = blockIdx.x*32, d0 = blockIdx.y*32;
    const int tx = threadIdx.x & 31, ty = threadIdx.x >> 5;
#pragma unroll
    for (int i=0;i<4;i++){
        int r = ty + i*8;
        tbuf[r][tx] = V[(long long)(b*SS + s0 + r)*HH + h*DHEAD + d0 + tx];
    }
    __syncthreads();
#pragma unroll
    for (int i=0;i<4;i++){
        int r = ty + i*8;
        float v = tbuf[tx][r];
        bf16 hh, ll; bsplit(v, hh, ll);
        long long o = (long long)(bh*DHEAD + d0 + r)*SS + s0 + tx;
        Vth[o] = hh; Vtl[o] = ll;
    }
}

// ---------------- reductions -------------------------------------------------
__device__ __forceinline__ float warp_sum(float v){
#pragma unroll
    for(int o=16;o;o>>=1) v += __shfl_xor_sync(0xffffffffu,v,o);
    return v;
}
__device__ __forceinline__ float warp_max(float v){
#pragma unroll
    for(int o=16;o;o>>=1) v = fmaxf(v,__shfl_xor_sync(0xffffffffu,v,o));
    return v;
}
template<int NW>
__device__ __forceinline__ float block_sum(float v, float* sh){
    v = warp_sum(v);
    if((threadIdx.x&31)==0) sh[threadIdx.x>>5]=v;
    __syncthreads();
    float t=0.f;
#pragma unroll
    for(int i=0;i<NW;i++) t+=sh[i];
    __syncthreads();
    return t;
}
template<int NW>
__device__ __forceinline__ float block_max(float v, float* sh){
    v = warp_max(v);
    if((threadIdx.x&31)==0) sh[threadIdx.x>>5]=v;
    __syncthreads();
    float t=-1e30f;
#pragma unroll
    for(int i=0;i<NW;i++) t=fmaxf(t,sh[i]);
    __syncthreads();
    return t;
}

// ---------------- token embedding + sinusoidal PE (+ split) -------------------
__global__ __launch_bounds__(256) void embed_kernel(
    const int* __restrict__ x, const float* __restrict__ emb,
    float* __restrict__ z, bf16* __restrict__ zh, bf16* __restrict__ zl)
{
    const int row = blockIdx.x;
    const int s = row & (SS-1);
    const int tok = x[row];
    const int t = threadIdx.x;
#pragma unroll
    for(int i=0;i<4;i++){
        int c = t + (i<<8);
        int half = c >> 1;
        float dv = expf(-(float)(2*half) * (9.210340371976184f/(float)HH));
        float ang = (float)s * dv;
        float pe = (c & 1) ? cosf(ang) : sinf(ang);
        float v = emb[(long long)tok*HH + c] + pe;
        long long o = (long long)row*HH + c;
        z[o] = v;
        bf16 hh, ll; bsplit(v, hh, ll);
        zh[o] = hh; zl[o] = ll;
    }
}

// ---------------- fused residual-add + LayerNorm (+ split) --------------------
__global__ __launch_bounds__(256) void add_ln_kernel(
    const float* __restrict__ X, const float* __restrict__ R,
    const float* __restrict__ g, const float* __restrict__ b,
    float* __restrict__ out, bf16* __restrict__ outh, bf16* __restrict__ outl)
{
    __shared__ float sh[8];
    const long long row = blockIdx.x;
    const float* x = X + row*HH;
    const float* r = R + row*HH;
    const int t = threadIdx.x;
    float v[4]; float s=0.f;
#pragma unroll
    for(int i=0;i<4;i++){ int c=t+(i<<8); v[i]=x[c]+r[c]; s+=v[i]; }
    float mean = block_sum<8>(s, sh) * (1.0f/(float)HH);
    float sq=0.f;
#pragma unroll
    for(int i=0;i<4;i++){ float d=v[i]-mean; sq+=d*d; }
    float var = block_sum<8>(sq, sh) * (1.0f/(float)HH);
    float rstd = rsqrtf(var + 1e-5f);
#pragma unroll
    for(int i=0;i<4;i++){
        int c=t+(i<<8);
        float o = (v[i]-mean)*rstd*g[c]+b[c];
        long long idx = row*HH + c;
        out[idx] = o;
        bf16 hh, ll; bsplit(o, hh, ll);
        outh[idx] = hh; outl[idx] = ll;
    }
}

// ---------------- causal masked softmax -> split probs + atten_last -----------
__global__ __launch_bounds__(128) void attn_softmax_kernel(
    const float* __restrict__ S, const int* __restrict__ lengths,
    bf16* __restrict__ ph, bf16* __restrict__ pl, float* __restrict__ attn_out)
{
    __shared__ float sh[4];
    const int idx = blockIdx.x;
    const int q = idx & (SS-1);
    const int b = idx >> 11;
    const float* srow = S + (long long)idx*SS;
    bf16* phr = ph + (long long)idx*SS;
    bf16* plr = pl + (long long)idx*SS;
    const int t = threadIdx.x;
    if (q >= lengths[b]) {
#pragma unroll
        for(int i=0;i<4;i++){ int k=t+(i<<7); phr[k] = __float2bfloat16(0.f); plr[k] = __float2bfloat16(0.f); }
        if (attn_out && t==0) attn_out[idx] = 0.f;
        return;
    }
    float v[4]; float m=-1e30f;
#pragma unroll
    for(int i=0;i<4;i++){ int k=t+(i<<7); v[i]=(k<=q)?srow[k]:-1e30f; m=fmaxf(m,v[i]); }
    m = block_max<4>(m, sh);
    float s=0.f;
#pragma unroll
    for(int i=0;i<4;i++){ v[i]=expf(v[i]-m); s+=v[i]; }
    s = block_sum<4>(s, sh);
    float r = 1.0f/s;
#pragma unroll
    for(int i=0;i<4;i++){
        int k=t+(i<<7);
        float p = v[i]*r;
        bf16 hh, ll; bsplit(p, hh, ll);
        phr[k] = hh; plr[k] = ll;
    }
    if (attn_out && t==0) attn_out[idx] = r;
}

// ---------------- in-place softmax over vocab (8000) -------------------------
__global__ __launch_bounds__(256) void vocab_softmax_kernel(float* __restrict__ logits)
{
    __shared__ float sh[8];
    const long long row = blockIdx.x;
    float* p = logits + row*VV;
    const int t = threadIdx.x;
    float v[32]; float m=-1e30f;
#pragma unroll
    for(int i=0;i<32;i++){ int k=t+(i<<8); v[i]=(k<VV)?p[k]:-1e30f; m=fmaxf(m,v[i]); }
    m = block_max<8>(m, sh);
    float s=0.f;
#pragma unroll
    for(int i=0;i<32;i++){ v[i]=expf(v[i]-m); s+=v[i]; }
    s = block_sum<8>(s, sh);
    float r = 1.0f/s;
#pragma unroll
    for(int i=0;i<32;i++){ int k=t+(i<<8); if(k<VV) p[k]=v[i]*r; }
}

// ---------------- host-side launch helper ------------------------------------
#define TG_SMEM (2*STG_BYTES)

static void launch_tgemm(const bf16*Ah,const bf16*Al,const bf16*Bh,const bf16*Bl,
    const float*bias, float*C, bf16*Ch, bf16*Cl,
    int M,int N,int K,int lda,int ldb,int ldc,float alpha,int Nst,bool gelu_ep,
    int batch,int divz,long long sA1,long long sA2,long long sB1,long long sB2,
    long long sC1,long long sC2)
{
    cudaFuncSetAttribute(tgemm<0>, cudaFuncAttributeMaxDynamicSharedMemorySize, TG_SMEM);
    cudaFuncSetAttribute(tgemm<1>, cudaFuncAttributeMaxDynamicSharedMemorySize, TG_SMEM);
    dim3 grid(N/128, M/128, batch);
    if (gelu_ep)
        tgemm<1><<<grid,256,TG_SMEM>>>(Ah,Al,Bh,Bl,bias,C,Ch,Cl,M,N,K,lda,ldb,ldc,alpha,Nst,divz,sA1,sA2,sB1,sB2,sC1,sC2);
    else
        tgemm<0><<<grid,256,TG_SMEM>>>(Ah,Al,Bh,Bl,bias,C,Ch,Cl,M,N,K,lda,ldb,ldc,alpha,Nst,divz,sA1,sA2,sB1,sB2,sC1,sC2);
}

#define GETSYM(var, sym) cudaGetSymbolAddress((void**)&var, sym)

extern "C" void kernel_launch(void* const* d_in, const int* in_sizes, int n_in,
                              void* d_out, int out_size)
{
    const int*   x       = (const int*)  d_in[0];
    const int*   lengths = (const int*)  d_in[1];
    const float* emb     = (const float*)d_in[2];
    const float* Wq = (const float*)d_in[3];
    const float* bq = (const float*)d_in[4];
    const float* Wk = (const float*)d_in[5];
    const float* bk = (const float*)d_in[6];
    const float* Wv = (const float*)d_in[7];
    const float* bv = (const float*)d_in[8];
    const float* W1 = (const float*)d_in[9];
    const float* b1 = (const float*)d_in[10];
    const float* W2 = (const float*)d_in[11];
    const float* b2 = (const float*)d_in[12];
    const float* g1 = (const float*)d_in[13];
    const float* be1= (const float*)d_in[14];
    const float* g2 = (const float*)d_in[15];
    const float* be2= (const float*)d_in[16];
    const float* Wfc= (const float*)d_in[17];
    const float* bfc= (const float*)d_in[18];
    float* out      = (float*)d_out;
    float* attn_out = out + (long long)NB*SS*VV;

    float *z,*z1,*v,*o,*gg,*s;
    GETSYM(z,g_z); GETSYM(z1,g_z1); GETSYM(v,g_v); GETSYM(o,g_o); GETSYM(gg,g_gg); GETSYM(s,g_s);
    bf16 *zh,*zl,*z1h,*z1l,*qh,*ql,*kh,*kl,*fh,*fl,*och,*ocl,*vth,*vtl,*ph,*pl;
    GETSYM(zh,g_zh); GETSYM(zl,g_zl); GETSYM(z1h,g_z1h); GETSYM(z1l,g_z1l);
    GETSYM(qh,g_qh); GETSYM(ql,g_ql); GETSYM(kh,g_kh); GETSYM(kl,g_kl);
    GETSYM(fh,g_fh); GETSYM(fl,g_fl); GETSYM(och,g_och); GETSYM(ocl,g_ocl);
    GETSYM(vth,g_vth); GETSYM(vtl,g_vtl); GETSYM(ph,g_ph); GETSYM(pl,g_pl);
    bf16 *Wqh,*Wql,*Wkh,*Wkl,*Wvh,*Wvl,*W1h,*W1l,*W2h,*W2l,*Wfh,*Wfl,*emh,*eml;
    GETSYM(Wqh,g_Wqh); GETSYM(Wql,g_Wql); GETSYM(Wkh,g_Wkh); GETSYM(Wkl,g_Wkl);
    GETSYM(Wvh,g_Wvh); GETSYM(Wvl,g_Wvl); GETSYM(W1h,g_W1h); GETSYM(W1l,g_W1l);
    GETSYM(W2h,g_W2h); GETSYM(W2l,g_W2l); GETSYM(Wfh,g_Wfh); GETSYM(Wfl,g_Wfl);
    GETSYM(emh,g_emh); GETSYM(eml,g_eml);

    const long long SH  = (long long)SS*HH;
    const long long SS2 = (long long)SS*SS;
    const long long SD  = (long long)SS*DHEAD;
    const int WN = LLAY*HH*HH;

    // ---- pre-split weights + padded emb ----
    split_kernel<<<WN/1024,256>>>(Wq, Wqh, Wql, WN);
    split_kernel<<<WN/1024,256>>>(Wk, Wkh, Wkl, WN);
    split_kernel<<<WN/1024,256>>>(Wv, Wvh, Wvl, WN);
    split_kernel<<<WN/1024,256>>>(W1, W1h, W1l, WN);
    split_kernel<<<WN/1024,256>>>(W2, W2h, W2l, WN);
    split_kernel<<<HH*HH/1024,256>>>(Wfc, Wfh, Wfl, HH*HH);
    emb_split_pad_kernel<<<VPAD*HH/1024,256>>>(emb, emh, eml);

    // ---- embedding + positional encoding ----
    embed_kernel<<<NTOK,256>>>(x, emb, z, zh, zl);

    for (int l=0;l<LLAY;l++){
        const long long wo = (long long)l*HH*HH;

        // Q,K projections -> split only; V -> fp32
        launch_tgemm(zh,zl, Wqh+wo,Wql+wo, bq+l*HH, nullptr, qh, ql,
                     NTOK,HH,HH, HH,HH,HH, 1.f,HH,false, 1,1,0,0,0,0,0,0);
        launch_tgemm(zh,zl, Wkh+wo,Wkl+wo, bk+l*HH, nullptr, kh, kl,
                     NTOK,HH,HH, HH,HH,HH, 1.f,HH,false, 1,1,0,0,0,0,0,0);
        launch_tgemm(zh,zl, Wvh+wo,Wvl+wo, bv+l*HH, v, nullptr, nullptr,
                     NTOK,HH,HH, HH,HH,HH, 1.f,HH,false, 1,1,0,0,0,0,0,0);

        // V -> Vt split [bh][dh][S]
        {
            dim3 gr(SS/32, DHEAD/32, NB*NHEADS);
            transpose_split_v<<<gr,256>>>(v, vth, vtl);
        }

        // scores: s[bh] = Q_bh @ K_bh^T / 32
        launch_tgemm(qh,ql, kh,kl, nullptr, s, nullptr, nullptr,
                     SS,SS,DHEAD, HH,HH,SS, 1.0f/32.0f,SS,false,
                     NB*NHEADS, NHEADS, SH, DHEAD, SH, DHEAD,
                     (long long)NHEADS*SS2, SS2);

        attn_softmax_kernel<<<NB*NHEADS*SS,128>>>(s, lengths, ph, pl,
                                                  (l==LLAY-1)?attn_out:nullptr);

        // O[bh] = P_bh @ Vt_bh^T  (NT), stored [B,H,S,dh] contiguous
        launch_tgemm(ph,pl, vth,vtl, nullptr, o, nullptr, nullptr,
                     SS,DHEAD,SS, SS,SS,DHEAD, 1.f,DHEAD,false,
                     NB*NHEADS, 1, SS2, 0, SD, 0, SD, 0);

        // faithful reshape bug == identity on flat memory
        add_ln_kernel<<<NTOK,256>>>(z, o, g1+l*HH, be1+l*HH, z1, z1h, z1l);

        // FFN
        launch_tgemm(z1h,z1l, W1h+wo,W1l+wo, b1+l*HH, nullptr, fh, fl,
                     NTOK,HH,HH, HH,HH,HH, 1.f,HH,true, 1,1,0,0,0,0,0,0);
        launch_tgemm(fh,fl, W2h+wo,W2l+wo, b2+l*HH, gg, nullptr, nullptr,
                     NTOK,HH,HH, HH,HH,HH, 1.f,HH,false, 1,1,0,0,0,0,0,0);

        add_ln_kernel<<<NTOK,256>>>(z1, gg, g2+l*HH, be2+l*HH, z, zh, zl);
    }

    // out_fc = z @ Wfc^T + bfc -> split
    launch_tgemm(zh,zl, Wfh,Wfl, bfc, nullptr, och, ocl,
                 NTOK,HH,HH, HH,HH,HH, 1.f,HH,false, 1,1,0,0,0,0,0,0);
    // logits = out_fc @ emb^T (padded to 8064; store guard 8000)
    launch_tgemm(och,ocl, emh,eml, nullptr, out, nullptr, nullptr,
                 NTOK,VPAD,HH, HH,HH,VV, 1.f,VV,false, 1,1,0,0,0,0,0,0);
    vocab_softmax_kernel<<<NTOK,256>>>(out);
}

// round 8
// speedup vs baseline: 2.7516x; 1.3386x over previous
#include <cuda_runtime.h>
#include <cuda_fp16.h>
#include <math.h>
#include <stdint.h>

// Problem dims (fixed by reference setup_inputs)
#define NB     16
#define SS     512
#define HH     1024
#define VV     8000
#define VPAD   8064            // pad vocab to multiple of 128
#define LLAY   8
#define NHEADS 4
#define DHEAD  256
#define NTOK   (NB*SS)          // 8192

typedef __half  f16;
typedef __half2 f162;

// ---------------- scratch (__device__ globals: no allocation allowed) ---------
__device__ float g_z  [NTOK*HH];
__device__ float g_z1 [NTOK*HH];
__device__ float g_v  [NTOK*HH];
__device__ float g_o  [NTOK*HH];
__device__ float g_gg [NTOK*HH];
__device__ float g_s  [NB*NHEADS*SS*SS];       // attention scores fp32

// A-side (split hi+lo)
__device__ f16 g_zh [NTOK*HH],  g_zl [NTOK*HH];
__device__ f16 g_z1h[NTOK*HH],  g_z1l[NTOK*HH];
__device__ f16 g_qh [NTOK*HH],  g_ql [NTOK*HH];
__device__ f16 g_fh [NTOK*HH],  g_fl [NTOK*HH];
__device__ f16 g_och[NTOK*HH],  g_ocl[NTOK*HH];
__device__ f16 g_ph [NB*NHEADS*SS*SS], g_pl [NB*NHEADS*SS*SS];
// B-side (single rounded fp16)
__device__ f16 g_kh [NTOK*HH];
__device__ f16 g_vth[NTOK*HH];                 // V^T [bh][dh][S]
__device__ f16 g_Wqh[LLAY*HH*HH];
__device__ f16 g_Wkh[LLAY*HH*HH];
__device__ f16 g_Wvh[LLAY*HH*HH];
__device__ f16 g_W1h[LLAY*HH*HH];
__device__ f16 g_W2h[LLAY*HH*HH];
__device__ f16 g_Wfh[HH*HH];
__device__ f16 g_emh[VPAD*HH];

// ---------------- helpers -----------------------------------------------------
__device__ __forceinline__ void hsplit(float x, f16& h, f16& l){
    h = __float2half(x);
    l = __float2half(x - __half2float(h));
}
__device__ __forceinline__ void mma_f16(float* c, const uint32_t* a, const uint32_t* b){
    asm volatile("mma.sync.aligned.m16n8k16.row.col.f32.f16.f16.f32 "
        "{%0,%1,%2,%3}, {%4,%5,%6,%7}, {%8,%9}, {%0,%1,%2,%3};"
        : "+f"(c[0]),"+f"(c[1]),"+f"(c[2]),"+f"(c[3])
        : "r"(a[0]),"r"(a[1]),"r"(a[2]),"r"(a[3]), "r"(b[0]),"r"(b[1]));
}
__device__ __forceinline__ uint32_t s2u(const void* p){
    uint32_t a;
    asm("{ .reg .u64 t; cvta.to.shared.u64 t, %1; cvt.u32.u64 %0, t; }" : "=r"(a) : "l"(p));
    return a;
}
__device__ __forceinline__ void cp16(uint32_t dst, const void* src){
    asm volatile("cp.async.cg.shared.global [%0], [%1], 16;" :: "r"(dst), "l"(src));
}

// ================= fp16x2 NT GEMM: pre-split A, rounded B, cp.async 3-stage ===
// C = alpha*(A @ B^T) + bias; optional exact GELU; optional fp16 (split) output.
// A: (Ah,Al) [M][K] row-major; B: Bh [N][K].
// Tile 128x128x32, 256 thr, warps 2(m)x4(n) = 64x32 each. 2 MMAs per acc per ks.
// SMEM per stage: Ah 8KB | Al 8KB | Bh 8KB. 3 stages.
// Batched via blockIdx.z: off = (z/divz)*s1 + (z%divz)*s2 (elements).
// M,K multiples of 128/32; N multiple of 128 (pad); store guard col<Nst.
#define STG_BYTES 24576
#define TG_SMEM   (3*STG_BYTES)

template<int EPI>
__global__ void __launch_bounds__(256,2) tgemm(
    const f16* __restrict__ Ah, const f16* __restrict__ Al,
    const f16* __restrict__ Bh,
    const float* __restrict__ bias,
    float* __restrict__ C, f16* __restrict__ Ch, f16* __restrict__ Cl,
    int M, int N, int K, int lda, int ldb, int ldc, float alpha, int Nst,
    int divz, long long sA1, long long sA2, long long sB1, long long sB2,
    long long sC1, long long sC2)
{
    extern __shared__ char smem[];
    const int z = blockIdx.z;
    const long long offA = (long long)(z/divz)*sA1 + (long long)(z%divz)*sA2;
    const long long offB = (long long)(z/divz)*sB1 + (long long)(z%divz)*sB2;
    const long long offC = (long long)(z/divz)*sC1 + (long long)(z%divz)*sC2;
    Ah += offA; Al += offA; Bh += offB;

    const int m0 = blockIdx.y*128, n0 = blockIdx.x*128;
    const int tid = threadIdx.x;
    const int wid = tid>>5, lane = tid&31;
    const int g = lane>>2, t = lane&3;
    const int m0w = (wid&1)*64, n0w = (wid>>1)*32;
    const int swz = g>>1;

    const uint32_t sb = s2u(smem);
    // staging map: op idx = tid + 256*r -> row = idx>>2 (0..127), ch = idx&3
    const int srow = tid>>2;
    const int sch  = tid&3;
    const uint32_t soff0 = (uint32_t)(srow*64 + ((sch  ^ ((srow>>1)&3))<<4));
    const int srow1 = (tid+256)>>2;
    const uint32_t soff1 = (uint32_t)(srow1*64 + ((sch ^ ((srow1>>1)&3))<<4));

    float acc[4][4][4];
#pragma unroll
    for (int i=0;i<4;i++)
#pragma unroll
        for (int j=0;j<4;j++)
#pragma unroll
            for (int r=0;r<4;r++) acc[i][j][r]=0.f;

    const int nch = K >> 5;

    auto stage_chunk = [&](int c, int st){
        const uint32_t base = sb + (uint32_t)st*STG_BYTES;
        const int kc = c*32;
        {
            const long long ga = (long long)(m0+srow)*lda + kc + sch*8;
            const long long gb = (long long)(n0+srow)*ldb + kc + sch*8;
            cp16(base +         soff0, Ah + ga);
            cp16(base +  8192 + soff0, Al + ga);
            cp16(base + 16384 + soff0, Bh + gb);
        }
        {
            const long long ga = (long long)(m0+srow1)*lda + kc + sch*8;
            const long long gb = (long long)(n0+srow1)*ldb + kc + sch*8;
            cp16(base +         soff1, Ah + ga);
            cp16(base +  8192 + soff1, Al + ga);
            cp16(base + 16384 + soff1, Bh + gb);
        }
        asm volatile("cp.async.commit_group;");
    };

    stage_chunk(0,0);
    stage_chunk(1,1);
    stage_chunk(2,2);

    for (int c=0; c<nch; c++){
        const int st = c % 3;
        asm volatile("cp.async.wait_group 2;");
        __syncthreads();

        const char* base = smem + st*STG_BYTES;
#pragma unroll
        for (int ks=0; ks<2; ks++){
            const int cs0 = ((ks*2  ) ^ swz)*16 + 4*t;
            const int cs1 = ((ks*2+1) ^ swz)*16 + 4*t;
            uint32_t bh[4][2];
#pragma unroll
            for (int j=0;j<4;j++){
                const int n = n0w + j*8 + g;
                bh[j][0] = *(const uint32_t*)(base + 16384 + n*64 + cs0);
                bh[j][1] = *(const uint32_t*)(base + 16384 + n*64 + cs1);
            }
#pragma unroll
            for (int i=0;i<4;i++){
                const int m = m0w + i*16 + g;
                const int p0 = m*64 + cs0, p1 = (m+8)*64 + cs0;
                const int p2 = m*64 + cs1, p3 = (m+8)*64 + cs1;
                uint32_t ah[4] = {
                    *(const uint32_t*)(base + p0), *(const uint32_t*)(base + p1),
                    *(const uint32_t*)(base + p2), *(const uint32_t*)(base + p3) };
                uint32_t al[4] = {
                    *(const uint32_t*)(base + 8192 + p0), *(const uint32_t*)(base + 8192 + p1),
                    *(const uint32_t*)(base + 8192 + p2), *(const uint32_t*)(base + 8192 + p3) };
#pragma unroll
                for (int j=0;j<4;j++){
                    mma_f16(acc[i][j], ah, bh[j]);
                    mma_f16(acc[i][j], al, bh[j]);
                }
            }
        }
        __syncthreads();
        if (c+3 < nch) stage_chunk(c+3, st);
    }

    // ---- epilogue ----
#pragma unroll
    for (int i=0;i<4;i++){
        const long long r0 = m0 + m0w + i*16 + g;
        const long long r1 = r0 + 8;
#pragma unroll
        for (int j=0;j<4;j++){
            const int col = n0 + n0w + j*8 + 2*t;
            if (col < Nst){
                float b0=0.f, b1=0.f;
                if (bias){ b0 = bias[col]; b1 = bias[col+1]; }
                float c0 = acc[i][j][0]*alpha + b0;
                float c1 = acc[i][j][1]*alpha + b1;
                float c2 = acc[i][j][2]*alpha + b0;
                float c3 = acc[i][j][3]*alpha + b1;
                if (EPI==1){
                    c0 = 0.5f*c0*(1.0f+erff(c0*0.70710678118654752440f));
                    c1 = 0.5f*c1*(1.0f+erff(c1*0.70710678118654752440f));
                    c2 = 0.5f*c2*(1.0f+erff(c2*0.70710678118654752440f));
                    c3 = 0.5f*c3*(1.0f+erff(c3*0.70710678118654752440f));
                }
                if (C){
                    *(float2*)&C[(offC + r0*ldc) + col] = make_float2(c0,c1);
                    *(float2*)&C[(offC + r1*ldc) + col] = make_float2(c2,c3);
                }
                if (Ch){
                    if (Cl){
                        f162 h0,l0,h1,l1;
                        hsplit(c0,h0.x,l0.x); hsplit(c1,h0.y,l0.y);
                        hsplit(c2,h1.x,l1.x); hsplit(c3,h1.y,l1.y);
                        *(f162*)&Ch[(offC + r0*ldc) + col] = h0;
                        *(f162*)&Cl[(offC + r0*ldc) + col] = l0;
                        *(f162*)&Ch[(offC + r1*ldc) + col] = h1;
                        *(f162*)&Cl[(offC + r1*ldc) + col] = l1;
                    } else {
                        *(f162*)&Ch[(offC + r0*ldc) + col] = __floats2half2_rn(c0,c1);
                        *(f162*)&Ch[(offC + r1*ldc) + col] = __floats2half2_rn(c2,c3);
                    }
                }
            }
        }
    }
}

// ---------------- weight round (hi only) kernels ------------------------------
__global__ __launch_bounds__(256) void round_kernel(
    const float* __restrict__ in, f16* __restrict__ h, int n)
{
    int i = (blockIdx.x*256 + threadIdx.x)*4;
    if (i < n){
        float4 v = *(const float4*)&in[i];
        *(f162*)&h[i]   = __floats2half2_rn(v.x, v.y);
        *(f162*)&h[i+2] = __floats2half2_rn(v.z, v.w);
    }
}
__global__ __launch_bounds__(256) void emb_round_pad_kernel(
    const float* __restrict__ emb, f16* __restrict__ h)
{
    int i = (blockIdx.x*256 + threadIdx.x)*4;         // over VPAD*HH
    int row = i >> 10;
    float4 v = make_float4(0.f,0.f,0.f,0.f);
    if (row < VV) v = *(const float4*)&emb[(long long)row*HH + (i & 1023)];
    *(f162*)&h[i]   = __floats2half2_rn(v.x, v.y);
    *(f162*)&h[i+2] = __floats2half2_rn(v.z, v.w);
}

// ---------------- V transpose + round: vt[(b,h)][d][s] ------------------------
__global__ __launch_bounds__(256) void transpose_round_v(
    const float* __restrict__ V, f16* __restrict__ Vth)
{
    __shared__ float tbuf[32][33];
    const int bh = blockIdx.z, b = bh >> 2, h = bh & 3;
    const int s0 = blockIdx.x*32, d0 = blockIdx.y*32;
    const int tx = threadIdx.x & 31, ty = threadIdx.x >> 5;
#pragma unroll
    for (int i=0;i<4;i++){
        int r = ty + i*8;
        tbuf[r][tx] = V[(long long)(b*SS + s0 + r)*HH + h*DHEAD + d0 + tx];
    }
    __syncthreads();
#pragma unroll
    for (int i=0;i<4;i++){
        int r = ty + i*8;
        Vth[(long long)(bh*DHEAD + d0 + r)*SS + s0 + tx] = __float2half(tbuf[tx][r]);
    }
}

// ---------------- reductions -------------------------------------------------
__device__ __forceinline__ float warp_sum(float v){
#pragma unroll
    for(int o=16;o;o>>=1) v += __shfl_xor_sync(0xffffffffu,v,o);
    return v;
}
__device__ __forceinline__ float warp_max(float v){
#pragma unroll
    for(int o=16;o;o>>=1) v = fmaxf(v,__shfl_xor_sync(0xffffffffu,v,o));
    return v;
}
template<int NW>
__device__ __forceinline__ float block_sum(float v, float* sh){
    v = warp_sum(v);
    if((threadIdx.x&31)==0) sh[threadIdx.x>>5]=v;
    __syncthreads();
    float t=0.f;
#pragma unroll
    for(int i=0;i<NW;i++) t+=sh[i];
    __syncthreads();
    return t;
}
template<int NW>
__device__ __forceinline__ float block_max(float v, float* sh){
    v = warp_max(v);
    if((threadIdx.x&31)==0) sh[threadIdx.x>>5]=v;
    __syncthreads();
    float t=-1e30f;
#pragma unroll
    for(int i=0;i<NW;i++) t=fmaxf(t,sh[i]);
    __syncthreads();
    return t;
}

// ---------------- token embedding + sinusoidal PE (+ split) -------------------
__global__ __launch_bounds__(256) void embed_kernel(
    const int* __restrict__ x, const float* __restrict__ emb,
    float* __restrict__ z, f16* __restrict__ zh, f16* __restrict__ zl)
{
    const int row = blockIdx.x;
    const int s = row & (SS-1);
    const int tok = x[row];
    const int t = threadIdx.x;
#pragma unroll
    for(int i=0;i<4;i++){
        int c = t + (i<<8);
        int half = c >> 1;
        float dv = expf(-(float)(2*half) * (9.210340371976184f/(float)HH));
        float ang = (float)s * dv;
        float pe = (c & 1) ? cosf(ang) : sinf(ang);
        float v = emb[(long long)tok*HH + c] + pe;
        long long o = (long long)row*HH + c;
        z[o] = v;
        f16 hh, ll; hsplit(v, hh, ll);
        zh[o] = hh; zl[o] = ll;
    }
}

// ---------------- fused residual-add + LayerNorm (+ split) --------------------
__global__ __launch_bounds__(256) void add_ln_kernel(
    const float* __restrict__ X, const float* __restrict__ R,
    const float* __restrict__ g, const float* __restrict__ b,
    float* __restrict__ out, f16* __restrict__ outh, f16* __restrict__ outl)
{
    __shared__ float sh[8];
    const long long row = blockIdx.x;
    const float* x = X + row*HH;
    const float* r = R + row*HH;
    const int t = threadIdx.x;
    float v[4]; float s=0.f;
#pragma unroll
    for(int i=0;i<4;i++){ int c=t+(i<<8); v[i]=x[c]+r[c]; s+=v[i]; }
    float mean = block_sum<8>(s, sh) * (1.0f/(float)HH);
    float sq=0.f;
#pragma unroll
    for(int i=0;i<4;i++){ float d=v[i]-mean; sq+=d*d; }
    float var = block_sum<8>(sq, sh) * (1.0f/(float)HH);
    float rstd = rsqrtf(var + 1e-5f);
#pragma unroll
    for(int i=0;i<4;i++){
        int c=t+(i<<8);
        float o = (v[i]-mean)*rstd*g[c]+b[c];
        long long idx = row*HH + c;
        out[idx] = o;
        f16 hh, ll; hsplit(o, hh, ll);
        outh[idx] = hh; outl[idx] = ll;
    }
}

// ---------------- causal masked softmax -> split probs + atten_last -----------
__global__ __launch_bounds__(128) void attn_softmax_kernel(
    const float* __restrict__ S, const int* __restrict__ lengths,
    f16* __restrict__ ph, f16* __restrict__ pl, float* __restrict__ attn_out)
{
    __shared__ float sh[4];
    const int idx = blockIdx.x;
    const int q = idx & (SS-1);
    const int b = idx >> 11;
    const float* srow = S + (long long)idx*SS;
    f16* phr = ph + (long long)idx*SS;
    f16* plr = pl + (long long)idx*SS;
    const int t = threadIdx.x;
    if (q >= lengths[b]) {
#pragma unroll
        for(int i=0;i<4;i++){ int k=t+(i<<7); phr[k] = __float2half(0.f); plr[k] = __float2half(0.f); }
        if (attn_out && t==0) attn_out[idx] = 0.f;
        return;
    }
    float v[4]; float m=-1e30f;
#pragma unroll
    for(int i=0;i<4;i++){ int k=t+(i<<7); v[i]=(k<=q)?srow[k]:-1e30f; m=fmaxf(m,v[i]); }
    m = block_max<4>(m, sh);
    float s=0.f;
#pragma unroll
    for(int i=0;i<4;i++){ v[i]=expf(v[i]-m); s+=v[i]; }
    s = block_sum<4>(s, sh);
    float r = 1.0f/s;
#pragma unroll
    for(int i=0;i<4;i++){
        int k=t+(i<<7);
        float p = v[i]*r;
        f16 hh, ll; hsplit(p, hh, ll);
        phr[k] = hh; plr[k] = ll;
    }
    if (attn_out && t==0) attn_out[idx] = r;
}

// ---------------- in-place softmax over vocab (8000) -------------------------
__global__ __launch_bounds__(256) void vocab_softmax_kernel(float* __restrict__ logits)
{
    __shared__ float sh[8];
    const long long row = blockIdx.x;
    float* p = logits + row*VV;
    const int t = threadIdx.x;
    float v[32]; float m=-1e30f;
#pragma unroll
    for(int i=0;i<32;i++){ int k=t+(i<<8); v[i]=(k<VV)?p[k]:-1e30f; m=fmaxf(m,v[i]); }
    m = block_max<8>(m, sh);
    float s=0.f;
#pragma unroll
    for(int i=0;i<32;i++){ v[i]=expf(v[i]-m); s+=v[i]; }
    s = block_sum<8>(s, sh);
    float r = 1.0f/s;
#pragma unroll
    for(int i=0;i<32;i++){ int k=t+(i<<8); if(k<VV) p[k]=v[i]*r; }
}

// ---------------- host-side launch helper ------------------------------------
static void launch_tgemm(const f16*Ah,const f16*Al,const f16*Bh,
    const float*bias, float*C, f16*Ch, f16*Cl,
    int M,int N,int K,int lda,int ldb,int ldc,float alpha,int Nst,bool gelu_ep,
    int batch,int divz,long long sA1,long long sA2,long long sB1,long long sB2,
    long long sC1,long long sC2)
{
    cudaFuncSetAttribute(tgemm<0>, cudaFuncAttributeMaxDynamicSharedMemorySize, TG_SMEM);
    cudaFuncSetAttribute(tgemm<1>, cudaFuncAttributeMaxDynamicSharedMemorySize, TG_SMEM);
    dim3 grid(N/128, M/128, batch);
    if (gelu_ep)
        tgemm<1><<<grid,256,TG_SMEM>>>(Ah,Al,Bh,bias,C,Ch,Cl,M,N,K,lda,ldb,ldc,alpha,Nst,divz,sA1,sA2,sB1,sB2,sC1,sC2);
    else
        tgemm<0><<<grid,256,TG_SMEM>>>(Ah,Al,Bh,bias,C,Ch,Cl,M,N,K,lda,ldb,ldc,alpha,Nst,divz,sA1,sA2,sB1,sB2,sC1,sC2);
}

#define GETSYM(var, sym) cudaGetSymbolAddress((void**)&var, sym)

extern "C" void kernel_launch(void* const* d_in, const int* in_sizes, int n_in,
                              void* d_out, int out_size)
{
    const int*   x       = (const int*)  d_in[0];
    const int*   lengths = (const int*)  d_in[1];
    const float* emb     = (const float*)d_in[2];
    const float* Wq = (const float*)d_in[3];
    const float* bq = (const float*)d_in[4];
    const float* Wk = (const float*)d_in[5];
    const float* bk = (const float*)d_in[6];
    const float* Wv = (const float*)d_in[7];
    const float* bv = (const float*)d_in[8];
    const float* W1 = (const float*)d_in[9];
    const float* b1 = (const float*)d_in[10];
    const float* W2 = (const float*)d_in[11];
    const float* b2 = (const float*)d_in[12];
    const float* g1 = (const float*)d_in[13];
    const float* be1= (const float*)d_in[14];
    const float* g2 = (const float*)d_in[15];
    const float* be2= (const float*)d_in[16];
    const float* Wfc= (const float*)d_in[17];
    const float* bfc= (const float*)d_in[18];
    float* out      = (float*)d_out;
    float* attn_out = out + (long long)NB*SS*VV;

    float *z,*z1,*v,*o,*gg,*s;
    GETSYM(z,g_z); GETSYM(z1,g_z1); GETSYM(v,g_v); GETSYM(o,g_o); GETSYM(gg,g_gg); GETSYM(s,g_s);
    f16 *zh,*zl,*z1h,*z1l,*qh,*ql,*fh,*fl,*och,*ocl,*ph,*pl,*kh,*vth;
    GETSYM(zh,g_zh); GETSYM(zl,g_zl); GETSYM(z1h,g_z1h); GETSYM(z1l,g_z1l);
    GETSYM(qh,g_qh); GETSYM(ql,g_ql); GETSYM(fh,g_fh); GETSYM(fl,g_fl);
    GETSYM(och,g_och); GETSYM(ocl,g_ocl); GETSYM(ph,g_ph); GETSYM(pl,g_pl);
    GETSYM(kh,g_kh); GETSYM(vth,g_vth);
    f16 *Wqh,*Wkh,*Wvh,*W1h,*W2h,*Wfh,*emh;
    GETSYM(Wqh,g_Wqh); GETSYM(Wkh,g_Wkh); GETSYM(Wvh,g_Wvh);
    GETSYM(W1h,g_W1h); GETSYM(W2h,g_W2h); GETSYM(Wfh,g_Wfh); GETSYM(emh,g_emh);

    const long long SH  = (long long)SS*HH;
    const long long SS2 = (long long)SS*SS;
    const long long SD  = (long long)SS*DHEAD;
    const int WN = LLAY*HH*HH;

    // ---- round weights to fp16 + padded emb ----
    round_kernel<<<WN/1024,256>>>(Wq, Wqh, WN);
    round_kernel<<<WN/1024,256>>>(Wk, Wkh, WN);
    round_kernel<<<WN/1024,256>>>(Wv, Wvh, WN);
    round_kernel<<<WN/1024,256>>>(W1, W1h, WN);
    round_kernel<<<WN/1024,256>>>(W2, W2h, WN);
    round_kernel<<<HH*HH/1024,256>>>(Wfc, Wfh, HH*HH);
    emb_round_pad_kernel<<<VPAD*HH/1024,256>>>(emb, emh);

    // ---- embedding + positional encoding ----
    embed_kernel<<<NTOK,256>>>(x, emb, z, zh, zl);

    for (int l=0;l<LLAY;l++){
        const long long wo = (long long)l*HH*HH;

        // Q split; K rounded-only; V fp32
        launch_tgemm(zh,zl, Wqh+wo, bq+l*HH, nullptr, qh, ql,
                     NTOK,HH,HH, HH,HH,HH, 1.f,HH,false, 1,1,0,0,0,0,0,0);
        launch_tgemm(zh,zl, Wkh+wo, bk+l*HH, nullptr, kh, nullptr,
                     NTOK,HH,HH, HH,HH,HH, 1.f,HH,false, 1,1,0,0,0,0,0,0);
        launch_tgemm(zh,zl, Wvh+wo, bv+l*HH, v, nullptr, nullptr,
                     NTOK,HH,HH, HH,HH,HH, 1.f,HH,false, 1,1,0,0,0,0,0,0);

        // V -> Vt (rounded) [bh][dh][S]
        {
            dim3 gr(SS/32, DHEAD/32, NB*NHEADS);
            transpose_round_v<<<gr,256>>>(v, vth);
        }

        // scores: s[bh] = Q_bh @ K_bh^T / 32
        launch_tgemm(qh,ql, kh, nullptr, s, nullptr, nullptr,
                     SS,SS,DHEAD, HH,HH,SS, 1.0f/32.0f,SS,false,
                     NB*NHEADS, NHEADS, SH, DHEAD, SH, DHEAD,
                     (long long)NHEADS*SS2, SS2);

        attn_softmax_kernel<<<NB*NHEADS*SS,128>>>(s, lengths, ph, pl,
                                                  (l==LLAY-1)?attn_out:nullptr);

        // O[bh] = P_bh @ Vt_bh^T  (NT), stored [B,H,S,dh] contiguous
        launch_tgemm(ph,pl, vth, nullptr, o, nullptr, nullptr,
                     SS,DHEAD,SS, SS,SS,DHEAD, 1.f,DHEAD,false,
                     NB*NHEADS, 1, SS2, 0, SD, 0, SD, 0);

        // faithful reshape bug == identity on flat memory
        add_ln_kernel<<<NTOK,256>>>(z, o, g1+l*HH, be1+l*HH, z1, z1h, z1l);

        // FFN
        launch_tgemm(z1h,z1l, W1h+wo, b1+l*HH, nullptr, fh, fl,
                     NTOK,HH,HH, HH,HH,HH, 1.f,HH,true, 1,1,0,0,0,0,0,0);
        launch_tgemm(fh,fl, W2h+wo, b2+l*HH, gg, nullptr, nullptr,
                     NTOK,HH,HH, HH,HH,HH, 1.f,HH,false, 1,1,0,0,0,0,0,0);

        add_ln_kernel<<<NTOK,256>>>(z1, gg, g2+l*HH, be2+l*HH, z, zh, zl);
    }

    // out_fc = z @ Wfc^T + bfc -> split
    launch_tgemm(zh,zl, Wfh, bfc, nullptr, och, ocl,
                 NTOK,HH,HH, HH,HH,HH, 1.f,HH,false, 1,1,0,0,0,0,0,0);
    // logits = out_fc @ emb^T (padded to 8064; store guard 8000)
    launch_tgemm(och,ocl, emh, nullptr, out, nullptr, nullptr,
                 NTOK,VPAD,HH, HH,HH,VV, 1.f,VV,false, 1,1,0,0,0,0,0,0);
    vocab_softmax_kernel<<<NTOK,256>>>(out);
}

// round 9
// speedup vs baseline: 3.0324x; 1.1021x over previous
#include <cuda_runtime.h>
#include <cuda_fp16.h>
#include <math.h>
#include <stdint.h>

// Problem dims (fixed by reference setup_inputs)
#define NB     16
#define SS     512
#define HH     1024
#define VV     8000
#define VPAD   8064            // pad vocab to multiple of 128
#define LLAY   8
#define NHEADS 4
#define DHEAD  256
#define NTOK   (NB*SS)          // 8192

typedef __half  f16;
typedef __half2 f162;

// ---------------- scratch (__device__ globals: no allocation allowed) ---------
__device__ float g_z  [NTOK*HH];
__device__ float g_z1 [NTOK*HH];
__device__ float g_v  [NTOK*HH];
__device__ float g_o  [NTOK*HH];
__device__ float g_gg [NTOK*HH];
__device__ float g_s  [NB*NHEADS*SS*SS];       // attention scores fp32

// A-side (split hi+lo)
__device__ f16 g_zh [NTOK*HH],  g_zl [NTOK*HH];
__device__ f16 g_z1h[NTOK*HH],  g_z1l[NTOK*HH];
__device__ f16 g_qh [NTOK*HH],  g_ql [NTOK*HH];
__device__ f16 g_fh [NTOK*HH],  g_fl [NTOK*HH];
__device__ f16 g_och[NTOK*HH],  g_ocl[NTOK*HH];
__device__ f16 g_ph [NB*NHEADS*SS*SS];         // P hi only
// B-side (single rounded fp16)
__device__ f16 g_kh [NTOK*HH];
__device__ f16 g_vth[NTOK*HH];                 // V^T [bh][dh][S]
__device__ f16 g_Wqh[LLAY*HH*HH];
__device__ f16 g_Wkh[LLAY*HH*HH];
__device__ f16 g_Wvh[LLAY*HH*HH];
__device__ f16 g_W1h[LLAY*HH*HH];
__device__ f16 g_W2h[LLAY*HH*HH];
__device__ f16 g_Wfh[HH*HH];
__device__ f16 g_emh[VPAD*HH];

// ---------------- helpers -----------------------------------------------------
__device__ __forceinline__ void hsplit(float x, f16& h, f16& l){
    h = __float2half(x);
    l = __float2half(x - __half2float(h));
}
__device__ __forceinline__ void mma_f16(float* c, const uint32_t* a, const uint32_t* b){
    asm volatile("mma.sync.aligned.m16n8k16.row.col.f32.f16.f16.f32 "
        "{%0,%1,%2,%3}, {%4,%5,%6,%7}, {%8,%9}, {%0,%1,%2,%3};"
        : "+f"(c[0]),"+f"(c[1]),"+f"(c[2]),"+f"(c[3])
        : "r"(a[0]),"r"(a[1]),"r"(a[2]),"r"(a[3]), "r"(b[0]),"r"(b[1]));
}
__device__ __forceinline__ void ldsm4(uint32_t* r, uint32_t addr){
    asm volatile("ldmatrix.sync.aligned.m8n8.x4.shared.b16 {%0,%1,%2,%3}, [%4];"
        : "=r"(r[0]),"=r"(r[1]),"=r"(r[2]),"=r"(r[3]) : "r"(addr));
}
__device__ __forceinline__ uint32_t s2u(const void* p){
    uint32_t a;
    asm("{ .reg .u64 t; cvta.to.shared.u64 t, %1; cvt.u32.u64 %0, t; }" : "=r"(a) : "l"(p));
    return a;
}
__device__ __forceinline__ void cp16(uint32_t dst, const void* src){
    asm volatile("cp.async.cg.shared.global [%0], [%1], 16;" :: "r"(dst), "l"(src));
}

// ================= fp16 NT GEMM: ldmatrix fragments, cp.async 3-stage =========
// C = alpha*(A @ B^T) + bias; optional exact GELU; optional fp16 (split) output.
// SPLITA=2: A = Ah+Al (hi/lo);  SPLITA=1: A = Ah only.
// Tile 128x128x32, 256 thr, warps 2(m)x4(n). SMEM stage: Ah 8K | Al 8K | Bh 8K.
// Batched via blockIdx.z: off = (z/divz)*s1 + (z%divz)*s2 (elements).
// causal!=0: skip tiles with n0 > m0+127 (masked-out upper triangle).
#define STG_BYTES 24576
#define TG_SMEM   (3*STG_BYTES)

template<int EPI, int SPLITA>
__global__ void __launch_bounds__(256,2) tgemm(
    const f16* __restrict__ Ah, const f16* __restrict__ Al,
    const f16* __restrict__ Bh,
    const float* __restrict__ bias,
    float* __restrict__ C, f16* __restrict__ Ch, f16* __restrict__ Cl,
    int M, int N, int K, int lda, int ldb, int ldc, float alpha, int Nst, int causal,
    int divz, long long sA1, long long sA2, long long sB1, long long sB2,
    long long sC1, long long sC2)
{
    extern __shared__ char smem[];
    const int m0 = blockIdx.y*128, n0 = blockIdx.x*128;
    if (causal && n0 > m0 + 127) return;      // fully-masked score tile

    const int z = blockIdx.z;
    const long long offA = (long long)(z/divz)*sA1 + (long long)(z%divz)*sA2;
    const long long offB = (long long)(z/divz)*sB1 + (long long)(z%divz)*sB2;
    const long long offC = (long long)(z/divz)*sC1 + (long long)(z%divz)*sC2;
    Ah += offA; Al += offA; Bh += offB;

    const int tid = threadIdx.x;
    const int wid = tid>>5, lane = tid&31;
    const int g = lane>>2, t = lane&3;
    const int m0w = (wid&1)*64, n0w = (wid>>1)*32;

    // ldmatrix lane constants
    const int a_ro = ((lane>>3)&1)*8 + (lane&7);   // row offset within 16
    const int a_kh = lane>>4;                      // k-half select
    const int a_sw = (a_ro>>1)&3;
    const int b_ro = (lane>>4)*8 + (lane&7);       // n-row offset within jpair
    const int b_kh = (lane>>3)&1;
    const int b_sw = (b_ro>>1)&3;

    const uint32_t sb = s2u(smem);
    // cp.async staging map: idx = tid + 256*r -> row = idx>>2, ch = idx&3
    const int srow = tid>>2;
    const int sch  = tid&3;
    const uint32_t soff0 = (uint32_t)(srow*64 + ((sch  ^ ((srow>>1)&3))<<4));
    const int srow1 = (tid+256)>>2;
    const uint32_t soff1 = (uint32_t)(srow1*64 + ((sch ^ ((srow1>>1)&3))<<4));

    float acc[4][4][4];
#pragma unroll
    for (int i=0;i<4;i++)
#pragma unroll
        for (int j=0;j<4;j++)
#pragma unroll
            for (int r=0;r<4;r++) acc[i][j][r]=0.f;

    const int nch = K >> 5;

    auto stage_chunk = [&](int c, int st){
        const uint32_t base = sb + (uint32_t)st*STG_BYTES;
        const int kc = c*32;
        {
            const long long ga = (long long)(m0+srow)*lda + kc + sch*8;
            const long long gb = (long long)(n0+srow)*ldb + kc + sch*8;
            cp16(base +         soff0, Ah + ga);
            if (SPLITA==2) cp16(base + 8192 + soff0, Al + ga);
            cp16(base + 16384 + soff0, Bh + gb);
        }
        {
            const long long ga = (long long)(m0+srow1)*lda + kc + sch*8;
            const long long gb = (long long)(n0+srow1)*ldb + kc + sch*8;
            cp16(base +         soff1, Ah + ga);
            if (SPLITA==2) cp16(base + 8192 + soff1, Al + ga);
            cp16(base + 16384 + soff1, Bh + gb);
        }
        asm volatile("cp.async.commit_group;");
    };

    stage_chunk(0,0);
    stage_chunk(1,1);
    stage_chunk(2,2);

    for (int c=0; c<nch; c++){
        const int st = c % 3;
        asm volatile("cp.async.wait_group 2;");
        __syncthreads();

        const uint32_t base = sb + (uint32_t)st*STG_BYTES;
#pragma unroll
        for (int ks=0; ks<2; ks++){
            // B fragments: 2 ldmatrix.x4 cover 4 j values
            uint32_t bh[4][2];
#pragma unroll
            for (int jp=0; jp<2; jp++){
                uint32_t r4[4];
                const uint32_t addrB = base + 16384u
                    + (uint32_t)(n0w + jp*16 + b_ro)*64u
                    + (uint32_t)(((ks*2 + b_kh) ^ b_sw)<<4);
                ldsm4(r4, addrB);
                bh[2*jp  ][0] = r4[0]; bh[2*jp  ][1] = r4[1];
                bh[2*jp+1][0] = r4[2]; bh[2*jp+1][1] = r4[3];
            }
#pragma unroll
            for (int i=0;i<4;i++){
                const uint32_t addrA = base
                    + (uint32_t)(m0w + i*16 + a_ro)*64u
                    + (uint32_t)(((ks*2 + a_kh) ^ a_sw)<<4);
                uint32_t ah[4];
                ldsm4(ah, addrA);
                uint32_t al[4];
                if (SPLITA==2) ldsm4(al, addrA + 8192u);
#pragma unroll
                for (int j=0;j<4;j++){
                    mma_f16(acc[i][j], ah, bh[j]);
                    if (SPLITA==2) mma_f16(acc[i][j], al, bh[j]);
                }
            }
        }
        __syncthreads();
        if (c+3 < nch) stage_chunk(c+3, st);
    }

    // ---- epilogue ----
#pragma unroll
    for (int i=0;i<4;i++){
        const long long r0 = m0 + m0w + i*16 + g;
        const long long r1 = r0 + 8;
#pragma unroll
        for (int j=0;j<4;j++){
            const int col = n0 + n0w + j*8 + 2*t;
            if (col < Nst){
                float b0=0.f, b1=0.f;
                if (bias){ b0 = bias[col]; b1 = bias[col+1]; }
                float c0 = acc[i][j][0]*alpha + b0;
                float c1 = acc[i][j][1]*alpha + b1;
                float c2 = acc[i][j][2]*alpha + b0;
                float c3 = acc[i][j][3]*alpha + b1;
                if (EPI==1){
                    c0 = 0.5f*c0*(1.0f+erff(c0*0.70710678118654752440f));
                    c1 = 0.5f*c1*(1.0f+erff(c1*0.70710678118654752440f));
                    c2 = 0.5f*c2*(1.0f+erff(c2*0.70710678118654752440f));
                    c3 = 0.5f*c3*(1.0f+erff(c3*0.70710678118654752440f));
                }
                if (C){
                    *(float2*)&C[(offC + r0*ldc) + col] = make_float2(c0,c1);
                    *(float2*)&C[(offC + r1*ldc) + col] = make_float2(c2,c3);
                }
                if (Ch){
                    if (Cl){
                        f162 h0,l0,h1,l1;
                        hsplit(c0,h0.x,l0.x); hsplit(c1,h0.y,l0.y);
                        hsplit(c2,h1.x,l1.x); hsplit(c3,h1.y,l1.y);
                        *(f162*)&Ch[(offC + r0*ldc) + col] = h0;
                        *(f162*)&Cl[(offC + r0*ldc) + col] = l0;
                        *(f162*)&Ch[(offC + r1*ldc) + col] = h1;
                        *(f162*)&Cl[(offC + r1*ldc) + col] = l1;
                    } else {
                        *(f162*)&Ch[(offC + r0*ldc) + col] = __floats2half2_rn(c0,c1);
                        *(f162*)&Ch[(offC + r1*ldc) + col] = __floats2half2_rn(c2,c3);
                    }
                }
            }
        }
    }
}

// ---------------- weight round (hi only) kernels ------------------------------
__global__ __launch_bounds__(256) void round_kernel(
    const float* __restrict__ in, f16* __restrict__ h, int n)
{
    int i = (blockIdx.x*256 + threadIdx.x)*4;
    if (i < n){
        float4 v = *(const float4*)&in[i];
        *(f162*)&h[i]   = __floats2half2_rn(v.x, v.y);
        *(f162*)&h[i+2] = __floats2half2_rn(v.z, v.w);
    }
}
__global__ __launch_bounds__(256) void emb_round_pad_kernel(
    const float* __restrict__ emb, f16* __restrict__ h)
{
    int i = (blockIdx.x*256 + threadIdx.x)*4;         // over VPAD*HH
    int row = i >> 10;
    float4 v = make_float4(0.f,0.f,0.f,0.f);
    if (row < VV) v = *(const float4*)&emb[(long long)row*HH + (i & 1023)];
    *(f162*)&h[i]   = __floats2half2_rn(v.x, v.y);
    *(f162*)&h[i+2] = __floats2half2_rn(v.z, v.w);
}

// ---------------- V transpose + round: vt[(b,h)][d][s] ------------------------
__global__ __launch_bounds__(256) void transpose_round_v(
    const float* __restrict__ V, f16* __restrict__ Vth)
{
    __shared__ float tbuf[32][33];
    const int bh = blockIdx.z, b = bh >> 2, h = bh & 3;
    const int s0 = blockIdx.x*32, d0 = blockIdx.y*32;
    const int tx = threadIdx.x & 31, ty = threadIdx.x >> 5;
#pragma unroll
    for (int i=0;i<4;i++){
        int r = ty + i*8;
        tbuf[r][tx] = V[(long long)(b*SS + s0 + r)*HH + h*DHEAD + d0 + tx];
    }
    __syncthreads();
#pragma unroll
    for (int i=0;i<4;i++){
        int r = ty + i*8;
        Vth[(long long)(bh*DHEAD + d0 + r)*SS + s0 + tx] = __float2half(tbuf[tx][r]);
    }
}

// ---------------- reductions -------------------------------------------------
__device__ __forceinline__ float warp_sum(float v){
#pragma unroll
    for(int o=16;o;o>>=1) v += __shfl_xor_sync(0xffffffffu,v,o);
    return v;
}
__device__ __forceinline__ float warp_max(float v){
#pragma unroll
    for(int o=16;o;o>>=1) v = fmaxf(v,__shfl_xor_sync(0xffffffffu,v,o));
    return v;
}
template<int NW>
__device__ __forceinline__ float block_sum(float v, float* sh){
    v = warp_sum(v);
    if((threadIdx.x&31)==0) sh[threadIdx.x>>5]=v;
    __syncthreads();
    float t=0.f;
#pragma unroll
    for(int i=0;i<NW;i++) t+=sh[i];
    __syncthreads();
    return t;
}
template<int NW>
__device__ __forceinline__ float block_max(float v, float* sh){
    v = warp_max(v);
    if((threadIdx.x&31)==0) sh[threadIdx.x>>5]=v;
    __syncthreads();
    float t=-1e30f;
#pragma unroll
    for(int i=0;i<NW;i++) t=fmaxf(t,sh[i]);
    __syncthreads();
    return t;
}

// ---------------- token embedding + sinusoidal PE (+ split) -------------------
__global__ __launch_bounds__(256) void embed_kernel(
    const int* __restrict__ x, const float* __restrict__ emb,
    float* __restrict__ z, f16* __restrict__ zh, f16* __restrict__ zl)
{
    const int row = blockIdx.x;
    const int s = row & (SS-1);
    const int tok = x[row];
    const int t = threadIdx.x;
#pragma unroll
    for(int i=0;i<4;i++){
        int c = t + (i<<8);
        int half = c >> 1;
        float dv = expf(-(float)(2*half) * (9.210340371976184f/(float)HH));
        float ang = (float)s * dv;
        float pe = (c & 1) ? cosf(ang) : sinf(ang);
        float v = emb[(long long)tok*HH + c] + pe;
        long long o = (long long)row*HH + c;
        z[o] = v;
        f16 hh, ll; hsplit(v, hh, ll);
        zh[o] = hh; zl[o] = ll;
    }
}

// ---------------- fused residual-add + LayerNorm (+ split) --------------------
__global__ __launch_bounds__(256) void add_ln_kernel(
    const float* __restrict__ X, const float* __restrict__ R,
    const float* __restrict__ g, const float* __restrict__ b,
    float* __restrict__ out, f16* __restrict__ outh, f16* __restrict__ outl)
{
    __shared__ float sh[8];
    const long long row = blockIdx.x;
    const float* x = X + row*HH;
    const float* r = R + row*HH;
    const int t = threadIdx.x;
    float v[4]; float s=0.f;
#pragma unroll
    for(int i=0;i<4;i++){ int c=t+(i<<8); v[i]=x[c]+r[c]; s+=v[i]; }
    float mean = block_sum<8>(s, sh) * (1.0f/(float)HH);
    float sq=0.f;
#pragma unroll
    for(int i=0;i<4;i++){ float d=v[i]-mean; sq+=d*d; }
    float var = block_sum<8>(sq, sh) * (1.0f/(float)HH);
    float rstd = rsqrtf(var + 1e-5f);
#pragma unroll
    for(int i=0;i<4;i++){
        int c=t+(i<<8);
        float o = (v[i]-mean)*rstd*g[c]+b[c];
        long long idx = row*HH + c;
        out[idx] = o;
        f16 hh, ll; hsplit(o, hh, ll);
        outh[idx] = hh; outl[idx] = ll;
    }
}

// ---------------- causal masked softmax -> P (hi only) + atten_last ----------
__global__ __launch_bounds__(128) void attn_softmax_kernel(
    const float* __restrict__ S, const int* __restrict__ lengths,
    f16* __restrict__ ph, float* __restrict__ attn_out)
{
    __shared__ float sh[4];
    const int idx = blockIdx.x;
    const int q = idx & (SS-1);
    const int b = idx >> 11;
    const float* srow = S + (long long)idx*SS;
    f16* phr = ph + (long long)idx*SS;
    const int t = threadIdx.x;
    if (q >= lengths[b]) {
#pragma unroll
        for(int i=0;i<4;i++){ int k=t+(i<<7); phr[k] = __float2half(0.f); }
        if (attn_out && t==0) attn_out[idx] = 0.f;
        return;
    }
    float v[4]; float m=-1e30f;
#pragma unroll
    for(int i=0;i<4;i++){ int k=t+(i<<7); v[i]=(k<=q)?srow[k]:-1e30f; m=fmaxf(m,v[i]); }
    m = block_max<4>(m, sh);
    float s=0.f;
#pragma unroll
    for(int i=0;i<4;i++){ v[i]=expf(v[i]-m); s+=v[i]; }
    s = block_sum<4>(s, sh);
    float r = 1.0f/s;
#pragma unroll
    for(int i=0;i<4;i++){ int k=t+(i<<7); phr[k] = __float2half(v[i]*r); }
    if (attn_out && t==0) attn_out[idx] = r;
}

// ---------------- in-place softmax over vocab (8000) -------------------------
__global__ __launch_bounds__(256) void vocab_softmax_kernel(float* __restrict__ logits)
{
    __shared__ float sh[8];
    const long long row = blockIdx.x;
    float* p = logits + row*VV;
    const int t = threadIdx.x;
    float v[32]; float m=-1e30f;
#pragma unroll
    for(int i=0;i<32;i++){ int k=t+(i<<8); v[i]=(k<VV)?p[k]:-1e30f; m=fmaxf(m,v[i]); }
    m = block_max<8>(m, sh);
    float s=0.f;
#pragma unroll
    for(int i=0;i<32;i++){ v[i]=expf(v[i]-m); s+=v[i]; }
    s = block_sum<8>(s, sh);
    float r = 1.0f/s;
#pragma unroll
    for(int i=0;i<32;i++){ int k=t+(i<<8); if(k<VV) p[k]=v[i]*r; }
}

// ---------------- host-side launch helper ------------------------------------
static void launch_tgemm(const f16*Ah,const f16*Al,const f16*Bh,
    const float*bias, float*C, f16*Ch, f16*Cl,
    int M,int N,int K,int lda,int ldb,int ldc,float alpha,int Nst,
    bool gelu_ep,int splita,int causal,
    int batch,int divz,long long sA1,long long sA2,long long sB1,long long sB2,
    long long sC1,long long sC2)
{
    cudaFuncSetAttribute(tgemm<0,2>, cudaFuncAttributeMaxDynamicSharedMemorySize, TG_SMEM);
    cudaFuncSetAttribute(tgemm<1,2>, cudaFuncAttributeMaxDynamicSharedMemorySize, TG_SMEM);
    cudaFuncSetAttribute(tgemm<0,1>, cudaFuncAttributeMaxDynamicSharedMemorySize, TG_SMEM);
    dim3 grid(N/128, M/128, batch);
    if (splita==1)
        tgemm<0,1><<<grid,256,TG_SMEM>>>(Ah,Al,Bh,bias,C,Ch,Cl,M,N,K,lda,ldb,ldc,alpha,Nst,causal,divz,sA1,sA2,sB1,sB2,sC1,sC2);
    else if (gelu_ep)
        tgemm<1,2><<<grid,256,TG_SMEM>>>(Ah,Al,Bh,bias,C,Ch,Cl,M,N,K,lda,ldb,ldc,alpha,Nst,causal,divz,sA1,sA2,sB1,sB2,sC1,sC2);
    else
        tgemm<0,2><<<grid,256,TG_SMEM>>>(Ah,Al,Bh,bias,C,Ch,Cl,M,N,K,lda,ldb,ldc,alpha,Nst,causal,divz,sA1,sA2,sB1,sB2,sC1,sC2);
}

#define GETSYM(var, sym) cudaGetSymbolAddress((void**)&var, sym)

extern "C" void kernel_launch(void* const* d_in, const int* in_sizes, int n_in,
                              void* d_out, int out_size)
{
    const int*   x       = (const int*)  d_in[0];
    const int*   lengths = (const int*)  d_in[1];
    const float* emb     = (const float*)d_in[2];
    const float* Wq = (const float*)d_in[3];
    const float* bq = (const float*)d_in[4];
    const float* Wk = (const float*)d_in[5];
    const float* bk = (const float*)d_in[6];
    const float* Wv = (const float*)d_in[7];
    const float* bv = (const float*)d_in[8];
    const float* W1 = (const float*)d_in[9];
    const float* b1 = (const float*)d_in[10];
    const float* W2 = (const float*)d_in[11];
    const float* b2 = (const float*)d_in[12];
    const float* g1 = (const float*)d_in[13];
    const float* be1= (const float*)d_in[14];
    const float* g2 = (const float*)d_in[15];
    const float* be2= (const float*)d_in[16];
    const float* Wfc= (const float*)d_in[17];
    const float* bfc= (const float*)d_in[18];
    float* out      = (float*)d_out;
    float* attn_out = out + (long long)NB*SS*VV;

    float *z,*z1,*v,*o,*gg,*s;
    GETSYM(z,g_z); GETSYM(z1,g_z1); GETSYM(v,g_v); GETSYM(o,g_o); GETSYM(gg,g_gg); GETSYM(s,g_s);
    f16 *zh,*zl,*z1h,*z1l,*qh,*ql,*fh,*fl,*och,*ocl,*ph,*kh,*vth;
    GETSYM(zh,g_zh); GETSYM(zl,g_zl); GETSYM(z1h,g_z1h); GETSYM(z1l,g_z1l);
    GETSYM(qh,g_qh); GETSYM(ql,g_ql); GETSYM(fh,g_fh); GETSYM(fl,g_fl);
    GETSYM(och,g_och); GETSYM(ocl,g_ocl); GETSYM(ph,g_ph);
    GETSYM(kh,g_kh); GETSYM(vth,g_vth);
    f16 *Wqh,*Wkh,*Wvh,*W1h,*W2h,*Wfh,*emh;
    GETSYM(Wqh,g_Wqh); GETSYM(Wkh,g_Wkh); GETSYM(Wvh,g_Wvh);
    GETSYM(W1h,g_W1h); GETSYM(W2h,g_W2h); GETSYM(Wfh,g_Wfh); GETSYM(emh,g_emh);

    const long long SH  = (long long)SS*HH;
    const long long SS2 = (long long)SS*SS;
    const long long SD  = (long long)SS*DHEAD;
    const int WN = LLAY*HH*HH;

    // ---- round weights to fp16 + padded emb ----
    round_kernel<<<WN/1024,256>>>(Wq, Wqh, WN);
    round_kernel<<<WN/1024,256>>>(Wk, Wkh, WN);
    round_kernel<<<WN/1024,256>>>(Wv, Wvh, WN);
    round_kernel<<<WN/1024,256>>>(W1, W1h, WN);
    round_kernel<<<WN/1024,256>>>(W2, W2h, WN);
    round_kernel<<<HH*HH/1024,256>>>(Wfc, Wfh, HH*HH);
    emb_round_pad_kernel<<<VPAD*HH/1024,256>>>(emb, emh);

    // ---- embedding + positional encoding ----
    embed_kernel<<<NTOK,256>>>(x, emb, z, zh, zl);

    for (int l=0;l<LLAY;l++){
        const long long wo = (long long)l*HH*HH;

        // Q split; K rounded-only; V fp32
        launch_tgemm(zh,zl, Wqh+wo, bq+l*HH, nullptr, qh, ql,
                     NTOK,HH,HH, HH,HH,HH, 1.f,HH,false,2,0, 1,1,0,0,0,0,0,0);
        launch_tgemm(zh,zl, Wkh+wo, bk+l*HH, nullptr, kh, nullptr,
                     NTOK,HH,HH, HH,HH,HH, 1.f,HH,false,2,0, 1,1,0,0,0,0,0,0);
        launch_tgemm(zh,zl, Wvh+wo, bv+l*HH, v, nullptr, nullptr,
                     NTOK,HH,HH, HH,HH,HH, 1.f,HH,false,2,0, 1,1,0,0,0,0,0,0);

        // V -> Vt (rounded) [bh][dh][S]
        {
            dim3 gr(SS/32, DHEAD/32, NB*NHEADS);
            transpose_round_v<<<gr,256>>>(v, vth);
        }

        // scores: s[bh] = Q_bh @ K_bh^T / 32   (causal tile skip)
        launch_tgemm(qh,ql, kh, nullptr, s, nullptr, nullptr,
                     SS,SS,DHEAD, HH,HH,SS, 1.0f/32.0f,SS,false,2,1,
                     NB*NHEADS, NHEADS, SH, DHEAD, SH, DHEAD,
                     (long long)NHEADS*SS2, SS2);

        attn_softmax_kernel<<<NB*NHEADS*SS,128>>>(s, lengths, ph,
                                                  (l==LLAY-1)?attn_out:nullptr);

        // O[bh] = P_bh @ Vt_bh^T  (NT), P hi-only
        launch_tgemm(ph,ph, vth, nullptr, o, nullptr, nullptr,
                     SS,DHEAD,SS, SS,SS,DHEAD, 1.f,DHEAD,false,1,0,
                     NB*NHEADS, 1, SS2, 0, SD, 0, SD, 0);

        // faithful reshape bug == identity on flat memory
        add_ln_kernel<<<NTOK,256>>>(z, o, g1+l*HH, be1+l*HH, z1, z1h, z1l);

        // FFN
        launch_tgemm(z1h,z1l, W1h+wo, b1+l*HH, nullptr, fh, fl,
                     NTOK,HH,HH, HH,HH,HH, 1.f,HH,true,2,0, 1,1,0,0,0,0,0,0);
        launch_tgemm(fh,fl, W2h+wo, b2+l*HH, gg, nullptr, nullptr,
                     NTOK,HH,HH, HH,HH,HH, 1.f,HH,false,2,0, 1,1,0,0,0,0,0,0);

        add_ln_kernel<<<NTOK,256>>>(z1, gg, g2+l*HH, be2+l*HH, z, zh, zl);
    }

    // out_fc = z @ Wfc^T + bfc -> split
    launch_tgemm(zh,zl, Wfh, bfc, nullptr, och, ocl,
                 NTOK,HH,HH, HH,HH,HH, 1.f,HH,false,2,0, 1,1,0,0,0,0,0,0);
    // logits = out_fc @ emb^T (padded to 8064; store guard 8000)
    launch_tgemm(och,ocl, emh, nullptr, out, nullptr, nullptr,
                 NTOK,VPAD,HH, HH,HH,VV, 1.f,VV,false,2,0, 1,1,0,0,0,0,0,0);
    vocab_softmax_kernel<<<NTOK,256>>>(out);
}

// round 10
// speedup vs baseline: 4.2077x; 1.3876x over previous
#include <cuda_runtime.h>
#include <cuda_fp16.h>
#include <math.h>
#include <stdint.h>

// Problem dims (fixed by reference setup_inputs)
#define NB     16
#define SS     512
#define HH     1024
#define VV     8000
#define VPAD   8064            // pad vocab to multiple of 128
#define LLAY   8
#define NHEADS 4
#define DHEAD  256
#define NTOK   (NB*SS)          // 8192

typedef __half  f16;
typedef __half2 f162;

// ---------------- scratch (__device__ globals: no allocation allowed) ---------
__device__ float g_z  [NTOK*HH];
__device__ float g_z1 [NTOK*HH];
__device__ float g_v  [NTOK*HH];
__device__ float g_o  [NTOK*HH];
__device__ float g_gg [NTOK*HH];
__device__ float g_s  [NB*NHEADS*SS*SS];       // attention scores fp32

// A-side (split hi+lo where needed)
__device__ f16 g_zh [NTOK*HH],  g_zl [NTOK*HH];
__device__ f16 g_z1h[NTOK*HH],  g_z1l[NTOK*HH];
__device__ f16 g_qh [NTOK*HH],  g_ql [NTOK*HH];
__device__ f16 g_fh [NTOK*HH],  g_fl [NTOK*HH];
__device__ f16 g_och[NTOK*HH],  g_ocl[NTOK*HH];
__device__ f16 g_ph [NB*NHEADS*SS*SS];         // P hi only
// B-side (single rounded fp16)
__device__ f16 g_kh [NTOK*HH];
__device__ f16 g_vth[NTOK*HH];                 // V^T [bh][dh][S]
__device__ f16 g_Wqh[LLAY*HH*HH];
__device__ f16 g_Wkh[LLAY*HH*HH];
__device__ f16 g_Wvh[LLAY*HH*HH];
__device__ f16 g_W1h[LLAY*HH*HH];
__device__ f16 g_W2h[LLAY*HH*HH];
__device__ f16 g_Wfh[HH*HH];
__device__ f16 g_emh[VPAD*HH];

// ---------------- helpers -----------------------------------------------------
__device__ __forceinline__ void hsplit(float x, f16& h, f16& l){
    h = __float2half(x);
    l = __float2half(x - __half2float(h));
}
__device__ __forceinline__ void mma_f16(float* c, const uint32_t* a, const uint32_t* b){
    asm volatile("mma.sync.aligned.m16n8k16.row.col.f32.f16.f16.f32 "
        "{%0,%1,%2,%3}, {%4,%5,%6,%7}, {%8,%9}, {%0,%1,%2,%3};"
        : "+f"(c[0]),"+f"(c[1]),"+f"(c[2]),"+f"(c[3])
        : "r"(a[0]),"r"(a[1]),"r"(a[2]),"r"(a[3]), "r"(b[0]),"r"(b[1]));
}
__device__ __forceinline__ void ldsm4(uint32_t* r, uint32_t addr){
    asm volatile("ldmatrix.sync.aligned.m8n8.x4.shared.b16 {%0,%1,%2,%3}, [%4];"
        : "=r"(r[0]),"=r"(r[1]),"=r"(r[2]),"=r"(r[3]) : "r"(addr));
}
__device__ __forceinline__ uint32_t s2u(const void* p){
    uint32_t a;
    asm("{ .reg .u64 t; cvta.to.shared.u64 t, %1; cvt.u32.u64 %0, t; }" : "=r"(a) : "l"(p));
    return a;
}
__device__ __forceinline__ void cp16(uint32_t dst, const void* src){
    asm volatile("cp.async.cg.shared.global [%0], [%1], 16;" :: "r"(dst), "l"(src));
}

// ================= fp16 NT GEMM: ldmatrix fragments, cp.async 3-stage =========
// C = alpha*(A @ B^T) + bias; optional exact GELU; optional fp16 (split) output.
// SPLITA=2: A = Ah+Al (hi/lo);  SPLITA=1: A = Ah only.
// Tile 128x128x32, 256 thr, warps 2(m)x4(n). SMEM stage: Ah 8K | Al 8K | Bh 8K.
// Batched via blockIdx.z: off = (z/divz)*s1 + (z%divz)*s2 (elements).
// causal!=0: skip tiles with n0 > m0+127 (masked-out upper triangle).
#define STG_BYTES 24576
#define TG_SMEM   (3*STG_BYTES)

template<int EPI, int SPLITA>
__global__ void __launch_bounds__(256,2) tgemm(
    const f16* __restrict__ Ah, const f16* __restrict__ Al,
    const f16* __restrict__ Bh,
    const float* __restrict__ bias,
    float* __restrict__ C, f16* __restrict__ Ch, f16* __restrict__ Cl,
    int M, int N, int K, int lda, int ldb, int ldc, float alpha, int Nst, int causal,
    int divz, long long sA1, long long sA2, long long sB1, long long sB2,
    long long sC1, long long sC2)
{
    extern __shared__ char smem[];
    const int m0 = blockIdx.y*128, n0 = blockIdx.x*128;
    if (causal && n0 > m0 + 127) return;      // fully-masked score tile

    const int z = blockIdx.z;
    const long long offA = (long long)(z/divz)*sA1 + (long long)(z%divz)*sA2;
    const long long offB = (long long)(z/divz)*sB1 + (long long)(z%divz)*sB2;
    const long long offC = (long long)(z/divz)*sC1 + (long long)(z%divz)*sC2;
    Ah += offA; Al += offA; Bh += offB;

    const int tid = threadIdx.x;
    const int wid = tid>>5, lane = tid&31;
    const int g = lane>>2, t = lane&3;
    const int m0w = (wid&1)*64, n0w = (wid>>1)*32;

    // ldmatrix lane constants
    const int a_ro = ((lane>>3)&1)*8 + (lane&7);   // row offset within 16
    const int a_kh = lane>>4;                      // k-half select
    const int a_sw = (a_ro>>1)&3;
    const int b_ro = (lane>>4)*8 + (lane&7);       // n-row offset within jpair
    const int b_kh = (lane>>3)&1;
    const int b_sw = (b_ro>>1)&3;

    const uint32_t sb = s2u(smem);
    // cp.async staging map: idx = tid + 256*r -> row = idx>>2, ch = idx&3
    const int srow = tid>>2;
    const int sch  = tid&3;
    const uint32_t soff0 = (uint32_t)(srow*64 + ((sch  ^ ((srow>>1)&3))<<4));
    const int srow1 = (tid+256)>>2;
    const uint32_t soff1 = (uint32_t)(srow1*64 + ((sch ^ ((srow1>>1)&3))<<4));

    float acc[4][4][4];
#pragma unroll
    for (int i=0;i<4;i++)
#pragma unroll
        for (int j=0;j<4;j++)
#pragma unroll
            for (int r=0;r<4;r++) acc[i][j][r]=0.f;

    const int nch = K >> 5;

    auto stage_chunk = [&](int c, int st){
        const uint32_t base = sb + (uint32_t)st*STG_BYTES;
        const int kc = c*32;
        {
            const long long ga = (long long)(m0+srow)*lda + kc + sch*8;
            const long long gb = (long long)(n0+srow)*ldb + kc + sch*8;
            cp16(base +         soff0, Ah + ga);
            if (SPLITA==2) cp16(base + 8192 + soff0, Al + ga);
            cp16(base + 16384 + soff0, Bh + gb);
        }
        {
            const long long ga = (long long)(m0+srow1)*lda + kc + sch*8;
            const long long gb = (long long)(n0+srow1)*ldb + kc + sch*8;
            cp16(base +         soff1, Ah + ga);
            if (SPLITA==2) cp16(base + 8192 + soff1, Al + ga);
            cp16(base + 16384 + soff1, Bh + gb);
        }
        asm volatile("cp.async.commit_group;");
    };

    stage_chunk(0,0);
    stage_chunk(1,1);
    stage_chunk(2,2);

    for (int c=0; c<nch; c++){
        const int st = c % 3;
        asm volatile("cp.async.wait_group 2;");
        __syncthreads();

        const uint32_t base = sb + (uint32_t)st*STG_BYTES;
#pragma unroll
        for (int ks=0; ks<2; ks++){
            // B fragments: 2 ldmatrix.x4 cover 4 j values
            uint32_t bh[4][2];
#pragma unroll
            for (int jp=0; jp<2; jp++){
                uint32_t r4[4];
                const uint32_t addrB = base + 16384u
                    + (uint32_t)(n0w + jp*16 + b_ro)*64u
                    + (uint32_t)(((ks*2 + b_kh) ^ b_sw)<<4);
                ldsm4(r4, addrB);
                bh[2*jp  ][0] = r4[0]; bh[2*jp  ][1] = r4[1];
                bh[2*jp+1][0] = r4[2]; bh[2*jp+1][1] = r4[3];
            }
#pragma unroll
            for (int i=0;i<4;i++){
                const uint32_t addrA = base
                    + (uint32_t)(m0w + i*16 + a_ro)*64u
                    + (uint32_t)(((ks*2 + a_kh) ^ a_sw)<<4);
                uint32_t ah[4];
                ldsm4(ah, addrA);
                uint32_t al[4];
                if (SPLITA==2) ldsm4(al, addrA + 8192u);
#pragma unroll
                for (int j=0;j<4;j++){
                    mma_f16(acc[i][j], ah, bh[j]);
                    if (SPLITA==2) mma_f16(acc[i][j], al, bh[j]);
                }
            }
        }
        __syncthreads();
        if (c+3 < nch) stage_chunk(c+3, st);
    }

    // ---- epilogue ----
#pragma unroll
    for (int i=0;i<4;i++){
        const long long r0 = m0 + m0w + i*16 + g;
        const long long r1 = r0 + 8;
#pragma unroll
        for (int j=0;j<4;j++){
            const int col = n0 + n0w + j*8 + 2*t;
            if (col < Nst){
                float b0=0.f, b1=0.f;
                if (bias){ b0 = bias[col]; b1 = bias[col+1]; }
                float c0 = acc[i][j][0]*alpha + b0;
                float c1 = acc[i][j][1]*alpha + b1;
                float c2 = acc[i][j][2]*alpha + b0;
                float c3 = acc[i][j][3]*alpha + b1;
                if (EPI==1){
                    c0 = 0.5f*c0*(1.0f+erff(c0*0.70710678118654752440f));
                    c1 = 0.5f*c1*(1.0f+erff(c1*0.70710678118654752440f));
                    c2 = 0.5f*c2*(1.0f+erff(c2*0.70710678118654752440f));
                    c3 = 0.5f*c3*(1.0f+erff(c3*0.70710678118654752440f));
                }
                if (C){
                    *(float2*)&C[(offC + r0*ldc) + col] = make_float2(c0,c1);
                    *(float2*)&C[(offC + r1*ldc) + col] = make_float2(c2,c3);
                }
                if (Ch){
                    if (Cl){
                        f162 h0,l0,h1,l1;
                        hsplit(c0,h0.x,l0.x); hsplit(c1,h0.y,l0.y);
                        hsplit(c2,h1.x,l1.x); hsplit(c3,h1.y,l1.y);
                        *(f162*)&Ch[(offC + r0*ldc) + col] = h0;
                        *(f162*)&Cl[(offC + r0*ldc) + col] = l0;
                        *(f162*)&Ch[(offC + r1*ldc) + col] = h1;
                        *(f162*)&Cl[(offC + r1*ldc) + col] = l1;
                    } else {
                        *(f162*)&Ch[(offC + r0*ldc) + col] = __floats2half2_rn(c0,c1);
                        *(f162*)&Ch[(offC + r1*ldc) + col] = __floats2half2_rn(c2,c3);
                    }
                }
            }
        }
    }
}

// ---------------- weight round (hi only) kernels ------------------------------
__global__ __launch_bounds__(256) void round_kernel(
    const float* __restrict__ in, f16* __restrict__ h, int n)
{
    int i = (blockIdx.x*256 + threadIdx.x)*4;
    if (i < n){
        float4 v = *(const float4*)&in[i];
        *(f162*)&h[i]   = __floats2half2_rn(v.x, v.y);
        *(f162*)&h[i+2] = __floats2half2_rn(v.z, v.w);
    }
}
__global__ __launch_bounds__(256) void emb_round_pad_kernel(
    const float* __restrict__ emb, f16* __restrict__ h)
{
    int i = (blockIdx.x*256 + threadIdx.x)*4;         // over VPAD*HH
    int row = i >> 10;
    float4 v = make_float4(0.f,0.f,0.f,0.f);
    if (row < VV) v = *(const float4*)&emb[(long long)row*HH + (i & 1023)];
    *(f162*)&h[i]   = __floats2half2_rn(v.x, v.y);
    *(f162*)&h[i+2] = __floats2half2_rn(v.z, v.w);
}

// ---------------- V transpose + round: vt[(b,h)][d][s] ------------------------
__global__ __launch_bounds__(256) void transpose_round_v(
    const float* __restrict__ V, f16* __restrict__ Vth)
{
    __shared__ float tbuf[32][33];
    const int bh = blockIdx.z, b = bh >> 2, h = bh & 3;
    const int s0 = blockIdx.x*32, d0 = blockIdx.y*32;
    const int tx = threadIdx.x & 31, ty = threadIdx.x >> 5;
#pragma unroll
    for (int i=0;i<4;i++){
        int r = ty + i*8;
        tbuf[r][tx] = V[(long long)(b*SS + s0 + r)*HH + h*DHEAD + d0 + tx];
    }
    __syncthreads();
#pragma unroll
    for (int i=0;i<4;i++){
        int r = ty + i*8;
        Vth[(long long)(bh*DHEAD + d0 + r)*SS + s0 + tx] = __float2half(tbuf[tx][r]);
    }
}

// ---------------- reductions -------------------------------------------------
__device__ __forceinline__ float warp_sum(float v){
#pragma unroll
    for(int o=16;o;o>>=1) v += __shfl_xor_sync(0xffffffffu,v,o);
    return v;
}
__device__ __forceinline__ float warp_max(float v){
#pragma unroll
    for(int o=16;o;o>>=1) v = fmaxf(v,__shfl_xor_sync(0xffffffffu,v,o));
    return v;
}
template<int NW>
__device__ __forceinline__ float block_sum(float v, float* sh){
    v = warp_sum(v);
    if((threadIdx.x&31)==0) sh[threadIdx.x>>5]=v;
    __syncthreads();
    float t=0.f;
#pragma unroll
    for(int i=0;i<NW;i++) t+=sh[i];
    __syncthreads();
    return t;
}
template<int NW>
__device__ __forceinline__ float block_max(float v, float* sh){
    v = warp_max(v);
    if((threadIdx.x&31)==0) sh[threadIdx.x>>5]=v;
    __syncthreads();
    float t=-1e30f;
#pragma unroll
    for(int i=0;i<NW;i++) t=fmaxf(t,sh[i]);
    __syncthreads();
    return t;
}

// ---------------- token embedding + sinusoidal PE (+ split) -------------------
__global__ __launch_bounds__(256) void embed_kernel(
    const int* __restrict__ x, const float* __restrict__ emb,
    float* __restrict__ z, f16* __restrict__ zh, f16* __restrict__ zl)
{
    const int row = blockIdx.x;
    const int s = row & (SS-1);
    const int tok = x[row];
    const int t = threadIdx.x;
#pragma unroll
    for(int i=0;i<4;i++){
        int c = t + (i<<8);
        int half = c >> 1;
        float dv = expf(-(float)(2*half) * (9.210340371976184f/(float)HH));
        float ang = (float)s * dv;
        float pe = (c & 1) ? cosf(ang) : sinf(ang);
        float v = emb[(long long)tok*HH + c] + pe;
        long long o = (long long)row*HH + c;
        z[o] = v;
        f16 hh, ll; hsplit(v, hh, ll);
        zh[o] = hh; zl[o] = ll;
    }
}

// ---------------- fused residual-add + LayerNorm (+ split) --------------------
__global__ __launch_bounds__(256) void add_ln_kernel(
    const float* __restrict__ X, const float* __restrict__ R,
    const float* __restrict__ g, const float* __restrict__ b,
    float* __restrict__ out, f16* __restrict__ outh, f16* __restrict__ outl)
{
    __shared__ float sh[8];
    const long long row = blockIdx.x;
    const float* x = X + row*HH;
    const float* r = R + row*HH;
    const int t = threadIdx.x;
    float v[4]; float s=0.f;
#pragma unroll
    for(int i=0;i<4;i++){ int c=t+(i<<8); v[i]=x[c]+r[c]; s+=v[i]; }
    float mean = block_sum<8>(s, sh) * (1.0f/(float)HH);
    float sq=0.f;
#pragma unroll
    for(int i=0;i<4;i++){ float d=v[i]-mean; sq+=d*d; }
    float var = block_sum<8>(sq, sh) * (1.0f/(float)HH);
    float rstd = rsqrtf(var + 1e-5f);
#pragma unroll
    for(int i=0;i<4;i++){
        int c=t+(i<<8);
        float o = (v[i]-mean)*rstd*g[c]+b[c];
        long long idx = row*HH + c;
        out[idx] = o;
        f16 hh, ll; hsplit(o, hh, ll);
        outh[idx] = hh; outl[idx] = ll;
    }
}

// ---------------- causal masked softmax -> P (hi only) + atten_last ----------
__global__ __launch_bounds__(128) void attn_softmax_kernel(
    const float* __restrict__ S, const int* __restrict__ lengths,
    f16* __restrict__ ph, float* __restrict__ attn_out)
{
    __shared__ float sh[4];
    const int idx = blockIdx.x;
    const int q = idx & (SS-1);
    const int b = idx >> 11;
    const float* srow = S + (long long)idx*SS;
    f16* phr = ph + (long long)idx*SS;
    const int t = threadIdx.x;
    if (q >= lengths[b]) {
#pragma unroll
        for(int i=0;i<4;i++){ int k=t+(i<<7); phr[k] = __float2half(0.f); }
        if (attn_out && t==0) attn_out[idx] = 0.f;
        return;
    }
    float v[4]; float m=-1e30f;
#pragma unroll
    for(int i=0;i<4;i++){ int k=t+(i<<7); v[i]=(k<=q)?srow[k]:-1e30f; m=fmaxf(m,v[i]); }
    m = block_max<4>(m, sh);
    float s=0.f;
#pragma unroll
    for(int i=0;i<4;i++){ v[i]=expf(v[i]-m); s+=v[i]; }
    s = block_sum<4>(s, sh);
    float r = 1.0f/s;
#pragma unroll
    for(int i=0;i<4;i++){ int k=t+(i<<7); phr[k] = __float2half(v[i]*r); }
    if (attn_out && t==0) attn_out[idx] = r;
}

// ---------------- in-place softmax over vocab (8000) -------------------------
__global__ __launch_bounds__(256) void vocab_softmax_kernel(float* __restrict__ logits)
{
    __shared__ float sh[8];
    const long long row = blockIdx.x;
    float* p = logits + row*VV;
    const int t = threadIdx.x;
    float v[32]; float m=-1e30f;
#pragma unroll
    for(int i=0;i<32;i++){ int k=t+(i<<8); v[i]=(k<VV)?p[k]:-1e30f; m=fmaxf(m,v[i]); }
    m = block_max<8>(m, sh);
    float s=0.f;
#pragma unroll
    for(int i=0;i<32;i++){ v[i]=expf(v[i]-m); s+=v[i]; }
    s = block_sum<8>(s, sh);
    float r = 1.0f/s;
#pragma unroll
    for(int i=0;i<32;i++){ int k=t+(i<<8); if(k<VV) p[k]=v[i]*r; }
}

// ---------------- host-side launch helper ------------------------------------
static void launch_tgemm(const f16*Ah,const f16*Al,const f16*Bh,
    const float*bias, float*C, f16*Ch, f16*Cl,
    int M,int N,int K,int lda,int ldb,int ldc,float alpha,int Nst,
    bool gelu_ep,int splita,int causal,
    int batch,int divz,long long sA1,long long sA2,long long sB1,long long sB2,
    long long sC1,long long sC2)
{
    cudaFuncSetAttribute(tgemm<0,2>, cudaFuncAttributeMaxDynamicSharedMemorySize, TG_SMEM);
    cudaFuncSetAttribute(tgemm<1,1>, cudaFuncAttributeMaxDynamicSharedMemorySize, TG_SMEM);
    cudaFuncSetAttribute(tgemm<0,1>, cudaFuncAttributeMaxDynamicSharedMemorySize, TG_SMEM);
    dim3 grid(N/128, M/128, batch);
    if (splita==1){
        if (gelu_ep)
            tgemm<1,1><<<grid,256,TG_SMEM>>>(Ah,Al,Bh,bias,C,Ch,Cl,M,N,K,lda,ldb,ldc,alpha,Nst,causal,divz,sA1,sA2,sB1,sB2,sC1,sC2);
        else
            tgemm<0,1><<<grid,256,TG_SMEM>>>(Ah,Al,Bh,bias,C,Ch,Cl,M,N,K,lda,ldb,ldc,alpha,Nst,causal,divz,sA1,sA2,sB1,sB2,sC1,sC2);
    } else {
        tgemm<0,2><<<grid,256,TG_SMEM>>>(Ah,Al,Bh,bias,C,Ch,Cl,M,N,K,lda,ldb,ldc,alpha,Nst,causal,divz,sA1,sA2,sB1,sB2,sC1,sC2);
    }
}

#define GETSYM(var, sym) cudaGetSymbolAddress((void**)&var, sym)

extern "C" void kernel_launch(void* const* d_in, const int* in_sizes, int n_in,
                              void* d_out, int out_size)
{
    const int*   x       = (const int*)  d_in[0];
    const int*   lengths = (const int*)  d_in[1];
    const float* emb     = (const float*)d_in[2];
    const float* Wq = (const float*)d_in[3];
    const float* bq = (const float*)d_in[4];
    const float* Wk = (const float*)d_in[5];
    const float* bk = (const float*)d_in[6];
    const float* Wv = (const float*)d_in[7];
    const float* bv = (const float*)d_in[8];
    const float* W1 = (const float*)d_in[9];
    const float* b1 = (const float*)d_in[10];
    const float* W2 = (const float*)d_in[11];
    const float* b2 = (const float*)d_in[12];
    const float* g1 = (const float*)d_in[13];
    const float* be1= (const float*)d_in[14];
    const float* g2 = (const float*)d_in[15];
    const float* be2= (const float*)d_in[16];
    const float* Wfc= (const float*)d_in[17];
    const float* bfc= (const float*)d_in[18];
    float* out      = (float*)d_out;
    float* attn_out = out + (long long)NB*SS*VV;

    float *z,*z1,*v,*o,*gg,*s;
    GETSYM(z,g_z); GETSYM(z1,g_z1); GETSYM(v,g_v); GETSYM(o,g_o); GETSYM(gg,g_gg); GETSYM(s,g_s);
    f16 *zh,*zl,*z1h,*z1l,*qh,*ql,*fh,*fl,*och,*ocl,*ph,*kh,*vth;
    GETSYM(zh,g_zh); GETSYM(zl,g_zl); GETSYM(z1h,g_z1h); GETSYM(z1l,g_z1l);
    GETSYM(qh,g_qh); GETSYM(ql,g_ql); GETSYM(fh,g_fh); GETSYM(fl,g_fl);
    GETSYM(och,g_och); GETSYM(ocl,g_ocl); GETSYM(ph,g_ph);
    GETSYM(kh,g_kh); GETSYM(vth,g_vth);
    f16 *Wqh,*Wkh,*Wvh,*W1h,*W2h,*Wfh,*emh;
    GETSYM(Wqh,g_Wqh); GETSYM(Wkh,g_Wkh); GETSYM(Wvh,g_Wvh);
    GETSYM(W1h,g_W1h); GETSYM(W2h,g_W2h); GETSYM(Wfh,g_Wfh); GETSYM(emh,g_emh);

    const long long SH  = (long long)SS*HH;
    const long long SS2 = (long long)SS*SS;
    const long long SD  = (long long)SS*DHEAD;
    const int WN = LLAY*HH*HH;

    // ---- round weights to fp16 + padded emb ----
    round_kernel<<<WN/1024,256>>>(Wq, Wqh, WN);
    round_kernel<<<WN/1024,256>>>(Wk, Wkh, WN);
    round_kernel<<<WN/1024,256>>>(Wv, Wvh, WN);
    round_kernel<<<WN/1024,256>>>(W1, W1h, WN);
    round_kernel<<<WN/1024,256>>>(W2, W2h, WN);
    round_kernel<<<HH*HH/1024,256>>>(Wfc, Wfh, HH*HH);
    emb_round_pad_kernel<<<VPAD*HH/1024,256>>>(emb, emh);

    // ---- embedding + positional encoding ----
    embed_kernel<<<NTOK,256>>>(x, emb, z, zh, zl);

    for (int l=0;l<LLAY;l++){
        const long long wo = (long long)l*HH*HH;

        // hidden-layer GEMMs: A rounded (hi only) — error absorbed by LayerNorm
        launch_tgemm(zh,zl, Wqh+wo, bq+l*HH, nullptr, qh, ql,
                     NTOK,HH,HH, HH,HH,HH, 1.f,HH,false,1,0, 1,1,0,0,0,0,0,0);
        launch_tgemm(zh,zl, Wkh+wo, bk+l*HH, nullptr, kh, nullptr,
                     NTOK,HH,HH, HH,HH,HH, 1.f,HH,false,1,0, 1,1,0,0,0,0,0,0);
        launch_tgemm(zh,zl, Wvh+wo, bv+l*HH, v, nullptr, nullptr,
                     NTOK,HH,HH, HH,HH,HH, 1.f,HH,false,1,0, 1,1,0,0,0,0,0,0);

        // V -> Vt (rounded) [bh][dh][S]
        {
            dim3 gr(SS/32, DHEAD/32, NB*NHEADS);
            transpose_round_v<<<gr,256>>>(v, vth);
        }

        // scores: keep Q split (atten_last is a direct output), causal tile skip
        launch_tgemm(qh,ql, kh, nullptr, s, nullptr, nullptr,
                     SS,SS,DHEAD, HH,HH,SS, 1.0f/32.0f,SS,false,2,1,
                     NB*NHEADS, NHEADS, SH, DHEAD, SH, DHEAD,
                     (long long)NHEADS*SS2, SS2);

        attn_softmax_kernel<<<NB*NHEADS*SS,128>>>(s, lengths, ph,
                                                  (l==LLAY-1)?attn_out:nullptr);

        // O[bh] = P_bh @ Vt_bh^T  (NT), P hi-only
        launch_tgemm(ph,ph, vth, nullptr, o, nullptr, nullptr,
                     SS,DHEAD,SS, SS,SS,DHEAD, 1.f,DHEAD,false,1,0,
                     NB*NHEADS, 1, SS2, 0, SD, 0, SD, 0);

        // faithful reshape bug == identity on flat memory
        add_ln_kernel<<<NTOK,256>>>(z, o, g1+l*HH, be1+l*HH, z1, z1h, z1l);

        // FFN: A rounded (hi only)
        launch_tgemm(z1h,z1l, W1h+wo, b1+l*HH, nullptr, fh, fl,
                     NTOK,HH,HH, HH,HH,HH, 1.f,HH,true,1,0, 1,1,0,0,0,0,0,0);
        launch_tgemm(fh,fl, W2h+wo, b2+l*HH, gg, nullptr, nullptr,
                     NTOK,HH,HH, HH,HH,HH, 1.f,HH,false,1,0, 1,1,0,0,0,0,0,0);

        add_ln_kernel<<<NTOK,256>>>(z1, gg, g2+l*HH, be2+l*HH, z, zh, zl);
    }

    // out_fc = z @ Wfc^T + bfc -> split   (keep A split: feeds direct output)
    launch_tgemm(zh,zl, Wfh, bfc, nullptr, och, ocl,
                 NTOK,HH,HH, HH,HH,HH, 1.f,HH,false,2,0, 1,1,0,0,0,0,0,0);
    // logits = out_fc @ emb^T (padded to 8064; store guard 8000), A split
    launch_tgemm(och,ocl, emh, nullptr, out, nullptr, nullptr,
                 NTOK,VPAD,HH, HH,HH,VV, 1.f,VV,false,2,0, 1,1,0,0,0,0,0,0);
    vocab_softmax_kernel<<<NTOK,256>>>(out);
}